// round 15
// baseline (speedup 1.0000x reference)
#include <cuda_runtime.h>
#include <math.h>
#include <stdint.h>

// ---------------------------------------------------------------------------
// SLAMv2: 14-layer MoE-attention transformer, segmented schedule.
// Round 15: R14 + softmax FUSED into the AV GEMM (stats prepass + A-fragment
// exp transform). Standalone row-softmax kernels removed (~1.36GB traffic).
// ---------------------------------------------------------------------------

namespace {
constexpr int B = 2, S = 1024, D = 1000, E = 20, HD = 50, TH = 3 * HD;
constexpr int HD_P = 52;
constexpr int EN = E * TH;    // 3000 — wide qkv N
constexpr int F = 2048, CYCLES = 3, L = 14;
constexpr int NP = 460;       // padded segment length
constexpr int ZS = B * E;     // 40 z per segment

constexpr long long NX = (long long)B * S * D;
constexpr long long OFF_X    = 0;
constexpr long long OFF_XNEW = OFF_X + NX;
constexpr long long OFF_T    = OFF_XNEW + NX;
constexpr long long OFF_X1   = OFF_T + NX;
constexpr long long OFF_Y    = OFF_X1 + NX;
constexpr long long OFF_A    = OFF_Y + NX;
constexpr long long OFF_ROUT = OFF_A + NX;
constexpr long long OFF_H    = OFF_ROUT + (long long)B * S * E;
constexpr long long OFF_QKV  = OFF_H + (long long)B * S * F;
constexpr long long OFF_SC   = OFF_QKV + (long long)B * E * 3 * S * HD_P;
constexpr long long OFF_EWP  = OFF_SC + (long long)B * E * S * S;  // [L][D][EN]
constexpr long long OFF_OWR  = OFF_EWP + (long long)L * D * EN;
constexpr long long OFF_W1R  = OFF_OWR + (long long)L * D * D;
constexpr long long OFF_W2R  = OFF_W1R + (long long)L * D * F;
constexpr long long N_ROWS4  = 4LL * B * NP;            // 3680 rows
constexpr long long OFF_T4   = OFF_W2R + (long long)L * F * D;
constexpr long long OFF_R4   = OFF_T4 + N_ROWS4 * D;
constexpr long long OFF_QKV4 = OFF_R4 + N_ROWS4 * E;
constexpr long long OFF_Y4   = OFF_QKV4 + 160LL * 3 * NP * HD_P;
constexpr long long OFF_A4   = OFF_Y4 + N_ROWS4 * D;
constexpr long long OFF_X14  = OFF_A4 + N_ROWS4 * D;
constexpr long long OFF_H4   = OFF_X14 + N_ROWS4 * D;
constexpr long long OFF_O4   = OFF_H4 + N_ROWS4 * F;
constexpr long long TOTAL    = OFF_O4 + N_ROWS4 * D;
// sco4 (160 * NP * NP = 33.86M) reuses OFF_SC region (41.9M) — checked.
}  // namespace

__device__ float g_scratch[TOTAL];
__device__ const int c_segN[4]  = {460, 409, 410, 410};
__device__ const int c_segST[4] = {0, 256, 460, 665};
__device__ const int c_segP1[4] = {460, 409, 410, 359};

struct GemmP {
  const float* A; const float* Bm; const float* bias; float* C;
  int M, N, K, lda, ldb, ldc;
  int aDiv; long long as1, as2;
  int bDiv; long long bs1, bs2;
  int cDiv; long long cs1, cs2;
  int biasDiv; long long biasS;
  long long splitStride;
  float scale;
  const float* rout; int routN;
  int zSeg;            // z's per segment (0 = no segment batching)
  long long bSeg;      // extra B offset per segment (layer stride)
  long long biasSeg;   // extra bias offset per segment
  int segFlags;        // 1: M=segN, 2: N=segN, 4: K=segN
};

__device__ __forceinline__ float to_tf32(float x) {
  asm("cvt.rna.tf32.f32 %0, %0;" : "+f"(x));
  return x;
}

__device__ __forceinline__ void cp16(uint32_t dst, const float* src, int bytes) {
  asm volatile("cp.async.cg.shared.global [%0], [%1], 16, %2;\n"
               :: "r"(dst), "l"(src), "r"(bytes));
}
__device__ __forceinline__ void cp_commit() {
  asm volatile("cp.async.commit_group;\n");
}
template <int N>
__device__ __forceinline__ void cp_wait() {
  asm volatile("cp.async.wait_group %0;\n" :: "n"(N));
}

// ---------------------------------------------------------------------------
// TF32 tensor-core GEMM; cp.async 4-stage ring; k-slot remap fragments.
// EPI: 0 +bias; 1 +bias,GELU(round); 2 *scale; 3 *routing(round);
//      6 +bias, wide-N qkv scatter (round).
// SOFT=1: A operand is raw attention scores; per-row softmax fused
//         (stats prepass + fragment transform to_tf32(exp(v-m)*inv)).
// ---------------------------------------------------------------------------
template <int BM, int BN, int WM, int WN, int BTRANS, int EPI, int SOFT = 0>
__global__ __launch_bounds__(256) void tmma_k(GemmP p) {
  constexpr int BK = 16, ST = 4;
  constexpr int SKA = BK + 4;
  constexpr int LDB0 = BN + 4;
  constexpr int ASZ = BM * SKA;
  constexpr int BSZ = BTRANS ? BN * SKA : BK * LDB0;
  constexpr int NWN = BN / WN;
  constexpr int MT = WM / 16, NT = WN / 8;
  constexpr int ACH = BM * 4;
  constexpr int AV_ = (ACH + 255) / 256;
  constexpr int BV_ = BN / 64;
  static_assert((BM / WM) * (BN / WN) == 8, "need 8 warps");

  extern __shared__ float sm[];
  float* As = sm;
  float* Bs = sm + ST * ASZ;
  float* stm = sm + ST * (ASZ + (long long)BSZ);  // [BM] row max (SOFT)
  float* sti = stm + BM;                          // [BM] row 1/sum (SOFT)
  const uint32_t a_u32 = (uint32_t)__cvta_generic_to_shared(As);
  const uint32_t b_u32 = (uint32_t)__cvta_generic_to_shared(Bs);

  const int z = blockIdx.z;
  int seg = 0;
  if (p.zSeg) seg = z / p.zSeg;
  const int Mloc = (p.segFlags & 1) ? c_segN[seg] : p.M;
  const int Nloc = (p.segFlags & 2) ? c_segN[seg] : p.N;
  const int Kloc = (p.segFlags & 4) ? c_segN[seg] : p.K;

  const float* Ab =
      p.A + (long long)(z / p.aDiv) * p.as1 + (long long)(z % p.aDiv) * p.as2;
  const float* Bb =
      p.Bm + (long long)(z / p.bDiv) * p.bs1 + (long long)(z % p.bDiv) * p.bs2 +
      (long long)seg * p.bSeg;
  float* Cb =
      p.C + (long long)(z / p.cDiv) * p.cs1 + (long long)(z % p.cDiv) * p.cs2;

  const int m0 = blockIdx.y * BM, n0 = blockIdx.x * BN;
  const int tid = threadIdx.x;
  const int warp = tid >> 5, lane = tid & 31;
  const int g = lane >> 2, t = lane & 3;
  const int wm = (warp / NWN) * WM, wn = (warp % NWN) * WN;

  auto issue = [&](int it) {
    const int s = it % ST;
    const int kb = it * BK;
#pragma unroll
    for (int v = 0; v < AV_; v++) {
      int idx = tid + v * 256;
      if ((ACH % 256) != 0 && idx >= ACH) break;
      int m = idx >> 2, c4 = (idx & 3) * 4;
      int gm = m0 + m, gk = kb + c4;
      int by = 0;
      if (gm < Mloc) {
        int rem = (Kloc - gk) * 4;
        by = rem > 16 ? 16 : (rem > 0 ? rem : 0);
      }
      const float* src = Ab + (long long)(by ? gm : 0) * p.lda + (by ? gk : 0);
      cp16(a_u32 + (uint32_t)(s * ASZ + m * SKA + c4) * 4u, src, by);
    }
    if (BTRANS == 0) {
#pragma unroll
      for (int v = 0; v < BV_; v++) {
        int idx = tid + v * 256;
        int kk = idx / (BN / 4), n4 = (idx % (BN / 4)) * 4;
        int gk = kb + kk, gn = n0 + n4;
        int by = 0;
        if (gk < Kloc) {
          int rem = (Nloc - gn) * 4;
          by = rem > 16 ? 16 : (rem > 0 ? rem : 0);
        }
        const float* src = Bb + (long long)(by ? gk : 0) * p.ldb + (by ? gn : 0);
        cp16(b_u32 + (uint32_t)(s * BSZ + kk * LDB0 + n4) * 4u, src, by);
      }
    } else {
#pragma unroll
      for (int v = 0; v < BV_; v++) {
        int idx = tid + v * 256;
        int n = idx >> 2, c4 = (idx & 3) * 4;
        int gn = n0 + n, gk = kb + c4;
        int by = 0;
        if (gn < Nloc) {
          int rem = (Kloc - gk) * 4;
          by = rem > 16 ? 16 : (rem > 0 ? rem : 0);
        }
        const float* src = Bb + (long long)(by ? gn : 0) * p.ldb + (by ? gk : 0);
        cp16(b_u32 + (uint32_t)(s * BSZ + n * SKA + c4) * 4u, src, by);
      }
    }
  };

  float c[MT][NT][4];
#pragma unroll
  for (int i = 0; i < MT; i++)
#pragma unroll
    for (int j = 0; j < NT; j++)
#pragma unroll
      for (int r = 0; r < 4; r++) c[i][j][r] = 0.f;

  auto comp = [&](int s) {
    const float* Asb = As + s * ASZ;
    const float* Bsb = Bs + s * BSZ;
#pragma unroll
    for (int kq = 0; kq < 2; kq++) {
      const int ko = kq * 8 + 2 * t;
      float2 af[MT][2];
#pragma unroll
      for (int mt = 0; mt < MT; mt++) {
        int r0 = wm + mt * 16 + g;
        af[mt][0] = *reinterpret_cast<const float2*>(&Asb[r0 * SKA + ko]);
        af[mt][1] = *reinterpret_cast<const float2*>(&Asb[(r0 + 8) * SKA + ko]);
        if (SOFT) {
          float m1 = stm[r0], i1 = sti[r0];
          float m2 = stm[r0 + 8], i2 = sti[r0 + 8];
          af[mt][0].x = to_tf32(__expf(af[mt][0].x - m1) * i1);
          af[mt][0].y = to_tf32(__expf(af[mt][0].y - m1) * i1);
          af[mt][1].x = to_tf32(__expf(af[mt][1].x - m2) * i2);
          af[mt][1].y = to_tf32(__expf(af[mt][1].y - m2) * i2);
        }
      }
      float bx[NT], by_[NT];
#pragma unroll
      for (int nt = 0; nt < NT; nt++) {
        int col = wn + nt * 8 + g;
        if (BTRANS == 1) {
          float2 bb = *reinterpret_cast<const float2*>(&Bsb[col * SKA + ko]);
          bx[nt] = bb.x;
          by_[nt] = bb.y;
        } else {
          bx[nt] = Bsb[ko * LDB0 + col];
          by_[nt] = Bsb[(ko + 1) * LDB0 + col];
        }
      }
#pragma unroll
      for (int mt = 0; mt < MT; mt++)
#pragma unroll
        for (int nt = 0; nt < NT; nt++) {
          asm volatile(
              "mma.sync.aligned.m16n8k8.row.col.f32.tf32.tf32.f32 "
              "{%0,%1,%2,%3}, {%4,%5,%6,%7}, {%8,%9}, {%0,%1,%2,%3};"
              : "+f"(c[mt][nt][0]), "+f"(c[mt][nt][1]), "+f"(c[mt][nt][2]),
                "+f"(c[mt][nt][3])
              : "r"(__float_as_uint(af[mt][0].x)),
                "r"(__float_as_uint(af[mt][1].x)),
                "r"(__float_as_uint(af[mt][0].y)),
                "r"(__float_as_uint(af[mt][1].y)),
                "r"(__float_as_uint(bx[nt])), "r"(__float_as_uint(by_[nt])));
        }
    }
  };

  const int iters = (Kloc + BK - 1) / BK;
#pragma unroll
  for (int s = 0; s < ST - 1; s++) {
    if (s < iters) issue(s);
    cp_commit();
  }

  if (SOFT) {
    // Row-stats prepass (overlaps the cp.async pipeline fill): per row of
    // this CTA's A pane, max + 1/sum(exp) over the valid Kloc columns.
    for (int r = warp; r < BM; r += 8) {
      int gm = m0 + r;
      float mx = 0.f, inv = 0.f;
      if (gm < Mloc) {
        const float* rp = Ab + (long long)gm * p.lda;
        mx = -1e30f;
        for (int j = lane; j < Kloc; j += 32) mx = fmaxf(mx, rp[j]);
#pragma unroll
        for (int o = 16; o; o >>= 1)
          mx = fmaxf(mx, __shfl_xor_sync(0xffffffffu, mx, o));
        float sum = 0.f;
        for (int j = lane; j < Kloc; j += 32) sum += __expf(rp[j] - mx);
#pragma unroll
        for (int o = 16; o; o >>= 1) sum += __shfl_xor_sync(0xffffffffu, sum, o);
        inv = 1.f / sum;
      }
      if (lane == 0) {
        stm[r] = mx;
        sti[r] = inv;
      }
    }
    __syncthreads();
  }

  for (int it = 0; it < iters; it++) {
    cp_wait<ST - 2>();
    __syncthreads();
    if (it + ST - 1 < iters) issue(it + ST - 1);
    cp_commit();
    comp(it % ST);
  }

  const float* biasb = nullptr;
  if ((EPI == 0 || EPI == 1 || EPI == 6) && p.bias)
    biasb = p.bias + (long long)(z % p.biasDiv) * p.biasS +
            (long long)seg * p.biasSeg;

#pragma unroll
  for (int mt = 0; mt < MT; mt++)
#pragma unroll
    for (int nt = 0; nt < NT; nt++)
#pragma unroll
      for (int r = 0; r < 4; r++) {
        int row = m0 + wm + mt * 16 + g + ((r >> 1) ? 8 : 0);
        int col = n0 + wn + nt * 8 + 2 * t + (r & 1);
        if (row >= Mloc || col >= Nloc) continue;
        float v = c[mt][nt][r];
        if (biasb) v += biasb[col];
        if (EPI == 1) {
          v = 0.5f * v * (1.f + erff(v * 0.70710678118654752f));
          v = to_tf32(v);
        }
        if (EPI == 2) v *= p.scale;
        if (EPI == 3) {
          v *= p.rout[((long long)(z / p.cDiv) * p.routN + row) * E +
                      (z % p.cDiv)];
          v = to_tf32(v);
        }
        if (EPI == 6) {
          // wide-N qkv scatter: col -> (e, h, s2); row -> (b, i).
          v = to_tf32(v);
          int e = col / TH;
          int th = col - e * TH;
          int h = th / HD;
          int s2 = th - h * HD;
          int b = row / p.routN;
          int i = row - b * p.routN;
          Cb[(long long)(b * E + e) * 3 * p.splitStride +
             (long long)h * p.splitStride + (long long)i * p.ldc + s2] = v;
        } else {
          Cb[(long long)row * p.ldc + col] = v;
        }
      }
}

// ---------------------------------------------------------------------------
// SIMT SGEMM (routing GEMM, N=20; fp32). z-batched via as1/bs1/cs1/biasS.
// ---------------------------------------------------------------------------
template <int BM, int BN, int BK, int TM, int TN>
__global__ __launch_bounds__((BM / TM) * (BN / TN)) void sgemm2_k(GemmP p) {
  constexpr int NTHR = (BM / TM) * (BN / TN);
  constexpr int TX = BN / TN;
  __shared__ float As[BK][BM + 4];
  __shared__ float Bs[BK][BN + 4];

  const int z = blockIdx.z;
  const float* Ab = p.A + (long long)z * p.as1;
  const float* Bb = p.Bm + (long long)z * p.bs1;
  float* Cb = p.C + (long long)z * p.cs1;
  const float* bias = p.bias ? p.bias + (long long)z * p.biasS : nullptr;

  const int m0 = blockIdx.y * BM, n0 = blockIdx.x * BN;
  const int tid = threadIdx.x;
  const int tx = tid % TX, ty = tid / TX;

  float acc[TM][TN];
#pragma unroll
  for (int i = 0; i < TM; i++)
#pragma unroll
    for (int j = 0; j < TN; j++) acc[i][j] = 0.f;

  for (int k0 = 0; k0 < p.K; k0 += BK) {
    for (int idx = tid; idx < BM * BK; idx += NTHR) {
      int m = idx / BK, kk = idx % BK;
      int gm = m0 + m, gk = k0 + kk;
      As[kk][m] = (gm < p.M && gk < p.K) ? Ab[(long long)gm * p.lda + gk] : 0.f;
    }
    for (int idx = tid; idx < BK * BN; idx += NTHR) {
      int kk = idx / BN, nn = idx % BN;
      int gk = k0 + kk, gn = n0 + nn;
      Bs[kk][nn] = (gk < p.K && gn < p.N) ? Bb[(long long)gk * p.ldb + gn] : 0.f;
    }
    __syncthreads();
#pragma unroll
    for (int kk = 0; kk < BK; kk++) {
      float a[TM], b[TN];
#pragma unroll
      for (int i = 0; i < TM; i++) a[i] = As[kk][ty * TM + i];
#pragma unroll
      for (int j = 0; j < TN; j++) b[j] = Bs[kk][tx * TN + j];
#pragma unroll
      for (int i = 0; i < TM; i++)
#pragma unroll
        for (int j = 0; j < TN; j++) acc[i][j] += a[i] * b[j];
    }
    __syncthreads();
  }

#pragma unroll
  for (int i = 0; i < TM; i++) {
    int row = m0 + ty * TM + i;
    if (row >= p.M) continue;
#pragma unroll
    for (int j = 0; j < TN; j++) {
      int col = n0 + tx * TN + j;
      if (col >= p.N) continue;
      float v = acc[i][j] + (bias ? bias[col] : 0.f);
      Cb[(long long)row * p.ldc + col] = v;
    }
  }
}

// ---------------------------------------------------------------------------
// One-launch weight prep: ew [L][E][D][TH] -> [L][D][E*TH] (tf32-rounded);
// ow/w1/w2 rounded in place layout.
// ---------------------------------------------------------------------------
__global__ void prep_k(float* sc, const float* ew, const float* ow,
                       const float* w1, const float* w2) {
  const long long n_ewp = (long long)L * D * EN;
  const long long n_ow = (long long)L * D * D;
  const long long n_w1 = (long long)L * D * F;
  const long long n_w2 = (long long)L * F * D;
  long long i = (long long)blockIdx.x * blockDim.x + threadIdx.x;
  if (i < n_ewp) {
    int col = (int)(i % EN);
    long long r = i / EN;
    int d = (int)(r % D);
    int l = (int)(r / D);
    int e = col / TH, th = col - e * TH;
    sc[OFF_EWP + i] =
        to_tf32(ew[(((long long)l * E + e) * D + d) * TH + th]);
    return;
  }
  i -= n_ewp;
  if (i < n_ow) { sc[OFF_OWR + i] = to_tf32(ow[i]); return; }
  i -= n_ow;
  if (i < n_w1) { sc[OFF_W1R + i] = to_tf32(w1[i]); return; }
  i -= n_w1;
  if (i < n_w2) { sc[OFF_W2R + i] = to_tf32(w2[i]); }
}

// ---------------------------------------------------------------------------
// Small kernels
// ---------------------------------------------------------------------------
__global__ void copy_round_k(float* dst, const float* src, long long n) {
  long long i = (long long)blockIdx.x * blockDim.x + threadIdx.x;
  if (i < n) dst[i] = to_tf32(src[i]);
}

__global__ void gather4_k(float* t4, const float* x) {
  long long idx = (long long)blockIdx.x * blockDim.x + threadIdx.x;
  long long tot = N_ROWS4 * D;
  if (idx >= tot) return;
  int d = (int)(idx % D);
  long long r = idx / D;
  int i = (int)(r % NP);
  int b = (int)((r / NP) % B);
  int j = (int)(r / ((long long)NP * B));
  if (i >= c_segN[j]) return;
  int si = (i < c_segP1[j]) ? c_segST[j] + i : i - c_segP1[j];
  t4[idx] = x[((long long)b * S + si) * D + d];
}

__device__ __forceinline__ float seg_cnt(int i) {
  float c = 0.f;
  c += (i < 460);
  c += (i >= 256 && i < 665);
  c += (i >= 460 && i < 870);
  c += (i >= 665);
  c += (i < 51);
  return c;
}

__global__ void combine_k(float* x, const float* o4) {
  long long idx = (long long)blockIdx.x * blockDim.x + threadIdx.x;
  if (idx >= NX) return;
  int d = (int)(idx % D);
  long long r = idx / D;
  int i = (int)(r % S);
  int b = (int)(r / S);
  float s = 0.f;
  if (i < 460) s += o4[(((0 * B + b) * (long long)NP + i) * D) + d];
  if (i >= 256 && i < 665)
    s += o4[(((1 * B + b) * (long long)NP + (i - 256)) * D) + d];
  if (i >= 460 && i < 870)
    s += o4[(((2 * B + b) * (long long)NP + (i - 460)) * D) + d];
  if (i >= 665) s += o4[(((3 * B + b) * (long long)NP + (i - 665)) * D) + d];
  if (i < 51) s += o4[(((3 * B + b) * (long long)NP + (359 + i)) * D) + d];
  x[idx] = to_tf32(s / seg_cnt(i));
}

__global__ void softmaxE_k(float* r, int rows) {
  int i = blockIdx.x * blockDim.x + threadIdx.x;
  if (i >= rows) return;
  float* p = r + (long long)i * E;
  float m = -1e30f;
  for (int e = 0; e < E; e++) m = fmaxf(m, p[e]);
  float s = 0.f;
  for (int e = 0; e < E; e++) {
    float v = __expf(p[e] - m);
    p[e] = v;
    s += v;
  }
  float inv = 1.f / s;
  for (int e = 0; e < E; e++) p[e] *= inv;
}

template <bool CVT, int SEGROWS>
__global__ void add_ln_k(const float* x, const float* r, const float* g,
                         const float* b, float* out) {
  long long base = (long long)blockIdx.x * D;
  if (SEGROWS > 0) {
    int seg = blockIdx.x / SEGROWS;
    g += (long long)seg * D;
    b += (long long)seg * D;
  }
  __shared__ float buf[D];
  __shared__ float redA[32], redB[32];
  __shared__ float sh_m, sh_inv;
  int tid = threadIdx.x;
  int nw = blockDim.x >> 5;

  float s = 0.f, s2 = 0.f;
  for (int d = tid; d < D; d += blockDim.x) {
    float v = x[base + d] + r[base + d];
    buf[d] = v;
    s += v;
    s2 += v * v;
  }
  for (int o = 16; o; o >>= 1) {
    s += __shfl_xor_sync(0xffffffffu, s, o);
    s2 += __shfl_xor_sync(0xffffffffu, s2, o);
  }
  if ((tid & 31) == 0) { redA[tid >> 5] = s; redB[tid >> 5] = s2; }
  __syncthreads();
  if (tid < 32) {
    float a2 = (tid < nw) ? redA[tid] : 0.f;
    float b2 = (tid < nw) ? redB[tid] : 0.f;
    for (int o = 16; o; o >>= 1) {
      a2 += __shfl_xor_sync(0xffffffffu, a2, o);
      b2 += __shfl_xor_sync(0xffffffffu, b2, o);
    }
    if (tid == 0) {
      float mean = a2 / D;
      float var = b2 / D - mean * mean;
      sh_m = mean;
      sh_inv = rsqrtf(var + 1e-5f);
    }
  }
  __syncthreads();
  float mean = sh_m, inv = sh_inv;
  for (int d = tid; d < D; d += blockDim.x) {
    float v = (buf[d] - mean) * inv * g[d] + b[d];
    out[base + d] = CVT ? to_tf32(v) : v;
  }
}

// ---------------------------------------------------------------------------
// Host-side driver
// ---------------------------------------------------------------------------
static inline int cdiv(int a, int b) { return (a + b - 1) / b; }

struct Wts {
  const float *ew, *eb, *rw, *rb, *ow, *ob, *l1g, *l1b, *w1, *b1, *w2, *b2,
      *l2g, *l2b;
};

constexpr int SMEM_128x64_T0 = 4 * (128 * 20 + 16 * 68) * 4;        // 58368
constexpr int SMEM_128x64_T0S = SMEM_128x64_T0 + 2 * 128 * 4;       // +stats
constexpr int SMEM_128x128_T1 = 4 * (128 * 20 + 128 * 20) * 4;      // 81920
constexpr int SMEM_128x128_T0 = 4 * (128 * 20 + 16 * 132) * 4;      // 74752

// -------------------- full-sequence block (layers 0 and 13) ----------------
static void run_block(float* sc, const float* t, float* out, int layer, int n,
                      const Wts& w) {
  const int M = B * n;
  const int n4 = (n + 3) & ~3;
  float* rout = sc + OFF_ROUT;
  float* qkv = sc + OFF_QKV;
  float* sco = sc + OFF_SC;
  float* y = sc + OFF_Y;
  float* a = sc + OFF_A;
  float* x1 = sc + OFF_X1;
  float* h = sc + OFF_H;
  const float* ewp = sc + OFF_EWP + (long long)layer * D * EN;
  const float* owr = sc + OFF_OWR + (long long)layer * D * D;
  const float* w1r = sc + OFF_W1R + (long long)layer * D * F;
  const float* w2r = sc + OFF_W2R + (long long)layer * F * D;

  GemmP p;
  auto reset = [&]() {
    p = GemmP{};
    p.aDiv = p.bDiv = p.cDiv = p.biasDiv = 1;
    p.scale = 1.f;
  };

  reset();
  p.A = t; p.Bm = w.rw + (long long)layer * D * E;
  p.bias = w.rb + (long long)layer * E; p.C = rout;
  p.M = M; p.N = E; p.K = D; p.lda = D; p.ldb = E; p.ldc = E;
  sgemm2_k<64, 64, 16, 4, 4><<<dim3(1, cdiv(M, 64), 1), 256>>>(p);
  softmaxE_k<<<cdiv(M, 256), 256>>>(rout, M);

  // qkv wide-N: [M, EN] = t @ ewp[layer] + eb, scattered to Q/K/V split
  reset();
  p.A = t; p.lda = D;
  p.Bm = ewp; p.ldb = EN;
  p.bias = w.eb + (long long)layer * E * TH;
  p.C = qkv; p.ldc = HD_P;
  p.splitStride = (long long)n * HD_P;
  p.routN = n;
  p.M = M; p.N = EN; p.K = D;
  tmma_k<128, 128, 64, 32, 0, 6>
      <<<dim3(cdiv(EN, 128), cdiv(M, 128), 1), 256, SMEM_128x128_T0>>>(p);

  reset();
  p.A = qkv; p.lda = HD_P; p.as1 = 3LL * n * HD_P;
  p.Bm = qkv + (long long)n * HD_P; p.ldb = HD_P; p.bs1 = 3LL * n * HD_P;
  p.C = sco; p.ldc = n4; p.cs1 = (long long)n * n4;
  p.M = n; p.N = n; p.K = HD;
  p.scale = 0.14142135623730950488f;
  tmma_k<128, 128, 64, 32, 1, 2>
      <<<dim3(cdiv(n, 128), cdiv(n, 128), B * E), 256, SMEM_128x128_T1>>>(p);

  // AV with fused softmax over raw scores
  reset();
  p.A = sco; p.lda = n4; p.as1 = (long long)n * n4;
  p.Bm = qkv + 2LL * n * HD_P; p.ldb = HD_P; p.bs1 = 3LL * n * HD_P;
  p.C = y; p.ldc = D; p.cDiv = E; p.cs1 = (long long)n * D; p.cs2 = HD;
  p.M = n; p.N = HD; p.K = n;
  p.rout = rout; p.routN = n;
  tmma_k<128, 64, 32, 32, 0, 3, 1>
      <<<dim3(1, cdiv(n, 128), B * E), 256, SMEM_128x64_T0S>>>(p);

  reset();
  p.A = y; p.lda = D;
  p.Bm = owr; p.ldb = D;
  p.bias = w.ob + (long long)layer * D;
  p.C = a; p.ldc = D;
  p.M = M; p.N = D; p.K = D;
  tmma_k<128, 128, 64, 32, 0, 0>
      <<<dim3(cdiv(D, 128), cdiv(M, 128), 1), 256, SMEM_128x128_T0>>>(p);

  add_ln_k<true, 0><<<M, 256>>>(t, a, w.l1g + (long long)layer * D,
                                w.l1b + (long long)layer * D, x1);

  reset();
  p.A = x1; p.lda = D;
  p.Bm = w1r; p.ldb = F;
  p.bias = w.b1 + (long long)layer * F;
  p.C = h; p.ldc = F;
  p.M = M; p.N = F; p.K = D;
  tmma_k<128, 128, 64, 32, 0, 1>
      <<<dim3(cdiv(F, 128), cdiv(M, 128), 1), 256, SMEM_128x128_T0>>>(p);

  reset();
  p.A = h; p.lda = F;
  p.Bm = w2r; p.ldb = D;
  p.bias = w.b2 + (long long)layer * D;
  p.C = y; p.ldc = D;
  p.M = M; p.N = D; p.K = F;
  tmma_k<128, 128, 64, 32, 0, 0>
      <<<dim3(cdiv(D, 128), cdiv(M, 128), 1), 256, SMEM_128x128_T0>>>(p);

  if (layer == L - 1)
    add_ln_k<false, 0><<<M, 256>>>(x1, y, w.l2g + (long long)layer * D,
                                   w.l2b + (long long)layer * D, out);
  else
    add_ln_k<true, 0><<<M, 256>>>(x1, y, w.l2g + (long long)layer * D,
                                  w.l2b + (long long)layer * D, out);
}

// -------------------- mega-batched 4-segment cycle --------------------------
static void run_segs(float* sc, int cyc, const Wts& w) {
  const int layerBase = 1 + 4 * cyc;
  const int MROWS = B * NP;          // 920 rows per segment
  const int NR4 = 4 * MROWS;         // 3680 rows total
  float* t4 = sc + OFF_T4;
  float* r4 = sc + OFF_R4;
  float* qkv4 = sc + OFF_QKV4;
  float* sco4 = sc + OFF_SC;
  float* y4 = sc + OFF_Y4;
  float* a4 = sc + OFF_A4;
  float* x14 = sc + OFF_X14;
  float* h4 = sc + OFF_H4;
  float* o4 = sc + OFF_O4;

  gather4_k<<<(int)((N_ROWS4 * D + 255) / 256), 256>>>(t4, sc + OFF_X);

  GemmP p;
  auto reset = [&]() {
    p = GemmP{};
    p.aDiv = p.bDiv = p.cDiv = p.biasDiv = 1;
    p.scale = 1.f;
  };

  // routing (z = 4 segments)
  reset();
  p.A = t4; p.lda = D; p.as1 = (long long)MROWS * D;
  p.Bm = w.rw + (long long)layerBase * D * E; p.ldb = E; p.bs1 = (long long)D * E;
  p.bias = w.rb + (long long)layerBase * E; p.biasS = E;
  p.C = r4; p.ldc = E; p.cs1 = (long long)MROWS * E;
  p.M = MROWS; p.N = E; p.K = D;
  sgemm2_k<64, 64, 16, 4, 4><<<dim3(1, cdiv(MROWS, 64), 4), 256>>>(p);
  softmaxE_k<<<cdiv(NR4, 256), 256>>>(r4, NR4);

  // qkv wide-N (z = 4 segments)
  reset();
  p.A = t4; p.lda = D; p.as1 = (long long)MROWS * D;
  p.Bm = sc + OFF_EWP + (long long)layerBase * D * EN; p.ldb = EN;
  p.bias = w.eb + (long long)layerBase * E * TH;
  p.C = qkv4; p.ldc = HD_P; p.cs1 = (long long)ZS * 3 * NP * HD_P;
  p.splitStride = (long long)NP * HD_P;
  p.routN = NP;
  p.M = MROWS; p.N = EN; p.K = D;
  p.zSeg = 1; p.bSeg = (long long)D * EN; p.biasSeg = (long long)E * TH;
  tmma_k<128, 128, 64, 32, 0, 6>
      <<<dim3(cdiv(EN, 128), cdiv(MROWS, 128), 4), 256, SMEM_128x128_T0>>>(p);

  // scores (z = 160)
  reset();
  p.A = qkv4; p.lda = HD_P; p.as1 = 3LL * NP * HD_P;
  p.Bm = qkv4 + (long long)NP * HD_P; p.ldb = HD_P; p.bs1 = 3LL * NP * HD_P;
  p.C = sco4; p.ldc = NP; p.cs1 = (long long)NP * NP;
  p.K = HD;
  p.scale = 0.14142135623730950488f;
  p.zSeg = ZS; p.segFlags = 1 | 2;
  tmma_k<128, 128, 64, 32, 1, 2>
      <<<dim3(cdiv(NP, 128), cdiv(NP, 128), 4 * ZS), 256, SMEM_128x128_T1>>>(p);

  // AV with fused softmax (z = 160)
  reset();
  p.A = sco4; p.lda = NP; p.as1 = (long long)NP * NP;
  p.Bm = qkv4 + 2LL * NP * HD_P; p.ldb = HD_P; p.bs1 = 3LL * NP * HD_P;
  p.C = y4; p.ldc = D; p.cDiv = E; p.cs1 = (long long)NP * D; p.cs2 = HD;
  p.N = HD;
  p.rout = r4; p.routN = NP;
  p.zSeg = ZS; p.segFlags = 1 | 4;
  tmma_k<128, 64, 32, 32, 0, 3, 1>
      <<<dim3(1, cdiv(NP, 128), 4 * ZS), 256, SMEM_128x64_T0S>>>(p);

  // out projection (z = 4)
  reset();
  p.A = y4; p.lda = D; p.as1 = (long long)MROWS * D;
  p.Bm = sc + OFF_OWR + (long long)layerBase * D * D; p.ldb = D;
  p.bias = w.ob + (long long)layerBase * D;
  p.C = a4; p.ldc = D; p.cs1 = (long long)MROWS * D;
  p.M = MROWS; p.N = D; p.K = D;
  p.zSeg = 1; p.bSeg = (long long)D * D; p.biasSeg = D;
  tmma_k<128, 128, 64, 32, 0, 0>
      <<<dim3(cdiv(D, 128), cdiv(MROWS, 128), 4), 256, SMEM_128x128_T0>>>(p);

  add_ln_k<true, B * NP><<<NR4, 256>>>(
      t4, a4, w.l1g + (long long)layerBase * D, w.l1b + (long long)layerBase * D,
      x14);

  // FF1 (z = 4)
  reset();
  p.A = x14; p.lda = D; p.as1 = (long long)MROWS * D;
  p.Bm = sc + OFF_W1R + (long long)layerBase * D * F; p.ldb = F;
  p.bias = w.b1 + (long long)layerBase * F;
  p.C = h4; p.ldc = F; p.cs1 = (long long)MROWS * F;
  p.M = MROWS; p.N = F; p.K = D;
  p.zSeg = 1; p.bSeg = (long long)D * F; p.biasSeg = F;
  tmma_k<128, 128, 64, 32, 0, 1>
      <<<dim3(cdiv(F, 128), cdiv(MROWS, 128), 4), 256, SMEM_128x128_T0>>>(p);

  // FF2 (z = 4) -> y4 (free after out projection)
  reset();
  p.A = h4; p.lda = F; p.as1 = (long long)MROWS * F;
  p.Bm = sc + OFF_W2R + (long long)layerBase * F * D; p.ldb = D;
  p.bias = w.b2 + (long long)layerBase * D;
  p.C = y4; p.ldc = D; p.cs1 = (long long)MROWS * D;
  p.M = MROWS; p.N = D; p.K = F;
  p.zSeg = 1; p.bSeg = (long long)F * D; p.biasSeg = D;
  tmma_k<128, 128, 64, 32, 0, 0>
      <<<dim3(cdiv(D, 128), cdiv(MROWS, 128), 4), 256, SMEM_128x128_T0>>>(p);

  add_ln_k<true, B * NP><<<NR4, 256>>>(
      x14, y4, w.l2g + (long long)layerBase * D,
      w.l2b + (long long)layerBase * D, o4);

  combine_k<<<cdiv((int)NX, 256), 256>>>(sc + OFF_X, o4);
}

extern "C" void kernel_launch(void* const* d_in, const int* in_sizes, int n_in,
                              void* d_out, int out_size) {
  (void)in_sizes; (void)n_in; (void)out_size;
  float* sc = nullptr;
  cudaGetSymbolAddress((void**)&sc, g_scratch);

  cudaFuncSetAttribute((const void*)tmma_k<128, 64, 32, 32, 0, 3, 1>,
                       cudaFuncAttributeMaxDynamicSharedMemorySize,
                       SMEM_128x64_T0S);
  cudaFuncSetAttribute((const void*)tmma_k<128, 128, 64, 32, 1, 2>,
                       cudaFuncAttributeMaxDynamicSharedMemorySize,
                       SMEM_128x128_T1);
  cudaFuncSetAttribute((const void*)tmma_k<128, 128, 64, 32, 0, 0>,
                       cudaFuncAttributeMaxDynamicSharedMemorySize,
                       SMEM_128x128_T0);
  cudaFuncSetAttribute((const void*)tmma_k<128, 128, 64, 32, 0, 1>,
                       cudaFuncAttributeMaxDynamicSharedMemorySize,
                       SMEM_128x128_T0);
  cudaFuncSetAttribute((const void*)tmma_k<128, 128, 64, 32, 0, 6>,
                       cudaFuncAttributeMaxDynamicSharedMemorySize,
                       SMEM_128x128_T0);

  const float* x_in = (const float*)d_in[0];
  Wts w;
  w.ew = (const float*)d_in[1];  w.eb = (const float*)d_in[2];
  w.rw = (const float*)d_in[3];  w.rb = (const float*)d_in[4];
  w.ow = (const float*)d_in[5];  w.ob = (const float*)d_in[6];
  w.l1g = (const float*)d_in[7]; w.l1b = (const float*)d_in[8];
  w.w1 = (const float*)d_in[9];  w.b1 = (const float*)d_in[10];
  w.w2 = (const float*)d_in[11]; w.b2 = (const float*)d_in[12];
  w.l2g = (const float*)d_in[13]; w.l2b = (const float*)d_in[14];

  {
    const long long tot = (long long)L * D * EN + (long long)L * D * D +
                          (long long)L * D * F + (long long)L * F * D;
    prep_k<<<(int)((tot + 255) / 256), 256>>>(sc, w.ew, w.ow, w.w1, w.w2);
  }

  copy_round_k<<<cdiv((int)NX, 256), 256>>>(sc + OFF_X, x_in, NX);

  run_block(sc, sc + OFF_X, sc + OFF_X, 0, S, w);

  for (int c = 0; c < CYCLES; c++) run_segs(sc, c, w);

  run_block(sc, sc + OFF_X, (float*)d_out, 13, S, w);
}

// round 16
// speedup vs baseline: 1.0857x; 1.0857x over previous
#include <cuda_runtime.h>
#include <math.h>
#include <stdint.h>

// ---------------------------------------------------------------------------
// SLAMv2: 14-layer MoE-attention transformer, segmented schedule.
// Round 16: flash-style fused attention (QK^T -> online softmax -> P@V in one
// kernel; scores never hit memory; P accumulators feed mma directly via the
// k-slot remap). Scores GEMM + softmax + AV launches removed (~2.3GB traffic).
// ---------------------------------------------------------------------------

namespace {
constexpr int B = 2, S = 1024, D = 1000, E = 20, HD = 50, TH = 3 * HD;
constexpr int HD_P = 52;
constexpr int EN = E * TH;    // 3000 — wide qkv N
constexpr int F = 2048, CYCLES = 3, L = 14;
constexpr int NP = 460;       // padded segment length
constexpr int ZS = B * E;     // 40 z per segment

constexpr long long NX = (long long)B * S * D;
constexpr long long OFF_X    = 0;
constexpr long long OFF_XNEW = OFF_X + NX;
constexpr long long OFF_T    = OFF_XNEW + NX;
constexpr long long OFF_X1   = OFF_T + NX;
constexpr long long OFF_Y    = OFF_X1 + NX;
constexpr long long OFF_A    = OFF_Y + NX;
constexpr long long OFF_ROUT = OFF_A + NX;
constexpr long long OFF_H    = OFF_ROUT + (long long)B * S * E;
constexpr long long OFF_QKV  = OFF_H + (long long)B * S * F;
constexpr long long OFF_SC   = OFF_QKV + (long long)B * E * 3 * S * HD_P;
constexpr long long OFF_EWP  = OFF_SC + (long long)B * E * S * S;  // [L][D][EN]
constexpr long long OFF_OWR  = OFF_EWP + (long long)L * D * EN;
constexpr long long OFF_W1R  = OFF_OWR + (long long)L * D * D;
constexpr long long OFF_W2R  = OFF_W1R + (long long)L * D * F;
constexpr long long N_ROWS4  = 4LL * B * NP;            // 3680 rows
constexpr long long OFF_T4   = OFF_W2R + (long long)L * F * D;
constexpr long long OFF_R4   = OFF_T4 + N_ROWS4 * D;
constexpr long long OFF_QKV4 = OFF_R4 + N_ROWS4 * E;
constexpr long long OFF_Y4   = OFF_QKV4 + 160LL * 3 * NP * HD_P;
constexpr long long OFF_A4   = OFF_Y4 + N_ROWS4 * D;
constexpr long long OFF_X14  = OFF_A4 + N_ROWS4 * D;
constexpr long long OFF_H4   = OFF_X14 + N_ROWS4 * D;
constexpr long long OFF_O4   = OFF_H4 + N_ROWS4 * F;
constexpr long long TOTAL    = OFF_O4 + N_ROWS4 * D;
}  // namespace

__device__ float g_scratch[TOTAL];
__device__ const int c_segN[4]  = {460, 409, 410, 410};
__device__ const int c_segST[4] = {0, 256, 460, 665};
__device__ const int c_segP1[4] = {460, 409, 410, 359};

struct GemmP {
  const float* A; const float* Bm; const float* bias; float* C;
  int M, N, K, lda, ldb, ldc;
  int aDiv; long long as1, as2;
  int bDiv; long long bs1, bs2;
  int cDiv; long long cs1, cs2;
  int biasDiv; long long biasS;
  long long splitStride;
  float scale;
  const float* rout; int routN;
  int zSeg;
  long long bSeg;
  long long biasSeg;
  int segFlags;
};

struct FaP {
  const float* qkv;          // Q base; K at +kOff, V at +vOff (per z)
  long long zStride, kOff, vOff;
  float* y; int cDiv; long long cs1, cs2; int ldc;
  const float* rout; int routN;
  int n;        // seq len (full blocks); segments use c_segN[z/zSeg]
  int zSeg;
  float scale;
};

__device__ __forceinline__ float to_tf32(float x) {
  asm("cvt.rna.tf32.f32 %0, %0;" : "+f"(x));
  return x;
}

__device__ __forceinline__ void cp16(uint32_t dst, const float* src, int bytes) {
  asm volatile("cp.async.cg.shared.global [%0], [%1], 16, %2;\n"
               :: "r"(dst), "l"(src), "r"(bytes));
}
__device__ __forceinline__ void cp_commit() {
  asm volatile("cp.async.commit_group;\n");
}
template <int N>
__device__ __forceinline__ void cp_wait() {
  asm volatile("cp.async.wait_group %0;\n" :: "n"(N));
}

__device__ __forceinline__ void mma8(float (&c)[4], float a0, float a1,
                                     float a2, float a3, float b0, float b1) {
  asm volatile(
      "mma.sync.aligned.m16n8k8.row.col.f32.tf32.tf32.f32 "
      "{%0,%1,%2,%3}, {%4,%5,%6,%7}, {%8,%9}, {%0,%1,%2,%3};"
      : "+f"(c[0]), "+f"(c[1]), "+f"(c[2]), "+f"(c[3])
      : "r"(__float_as_uint(a0)), "r"(__float_as_uint(a1)),
        "r"(__float_as_uint(a2)), "r"(__float_as_uint(a3)),
        "r"(__float_as_uint(b0)), "r"(__float_as_uint(b1)));
}

// ---------------------------------------------------------------------------
// Flash-style fused attention: per CTA = (z, 128-query tile).
// Warp tile: 16 query rows x 64 keys (S), 16 x 56 (O). Online softmax.
// ---------------------------------------------------------------------------
__global__ __launch_bounds__(256) void fattn_k(FaP p) {
  constexpr int QT = 128, KT = 64, SK = 56, HC = 7;
  extern __shared__ float sm[];
  float* Qs = sm;                      // [QT][SK]
  float* Ks = sm + QT * SK;            // [2][KT][SK]
  float* Vs = Ks + 2 * KT * SK;        // [2][KT][SK]
  const uint32_t q_u = (uint32_t)__cvta_generic_to_shared(Qs);
  const uint32_t k_u = (uint32_t)__cvta_generic_to_shared(Ks);
  const uint32_t v_u = (uint32_t)__cvta_generic_to_shared(Vs);

  const int z = blockIdx.y;
  const int nloc = p.zSeg ? c_segN[z / p.zSeg] : p.n;
  const float* Qb = p.qkv + (long long)z * p.zStride;
  const float* Kb = Qb + p.kOff;
  const float* Vb = Qb + p.vOff;

  const int m0 = blockIdx.x * QT;
  const int tid = threadIdx.x, warp = tid >> 5, lane = tid & 31;
  const int g = lane >> 2, t = lane & 3;
  const int r1 = warp * 16 + g;  // local query row (and +8)

  auto issueQ = [&]() {
#pragma unroll
    for (int v = 0; v < 7; v++) {
      int idx = tid + v * 256;
      int row = idx / 14, c = idx % 14;
      int gm = m0 + row;
      int by = 0;
      if (gm < nloc) {
        int rem = (HD - c * 4) * 4;
        by = rem > 16 ? 16 : (rem > 0 ? rem : 0);
      }
      const float* src = Qb + (by ? (long long)gm * HD_P + c * 4 : 0);
      cp16(q_u + (uint32_t)(row * SK + c * 4) * 4u, src, by);
    }
  };
  auto issueKV = [&](int kt, int s) {
#pragma unroll
    for (int v = 0; v < 7; v++) {
      int idx = tid + v * 256;
      int half = idx / 896;
      int rr = (idx % 896) / 14, c = idx % 14;
      int gk = kt * KT + rr;
      int by = 0;
      if (gk < nloc) {
        int rem = (HD - c * 4) * 4;
        by = rem > 16 ? 16 : (rem > 0 ? rem : 0);
      }
      const float* base = half ? Vb : Kb;
      const float* src = base + (by ? (long long)gk * HD_P + c * 4 : 0);
      uint32_t dst = (half ? v_u : k_u) +
                     (uint32_t)(s * KT * SK + rr * SK + c * 4) * 4u;
      cp16(dst, src, by);
    }
  };

  const int T = (nloc + KT - 1) / KT;
  issueQ();
  issueKV(0, 0);
  cp_commit();
  if (T > 1) issueKV(1, 1);
  cp_commit();

  float o[7][4];
#pragma unroll
  for (int i = 0; i < 7; i++)
#pragma unroll
    for (int r = 0; r < 4; r++) o[i][r] = 0.f;
  float m_run[2] = {-1e30f, -1e30f};
  float s_run[2] = {0.f, 0.f};

  for (int kt = 0; kt < T; kt++) {
    cp_wait<1>();
    __syncthreads();
    const float* Ksb = Ks + (kt & 1) * KT * SK;
    const float* Vsb = Vs + (kt & 1) * KT * SK;

    // S = Q @ K^T (warp: 16 rows x 64 keys), accum fp32
    float sa[8][4];
#pragma unroll
    for (int i = 0; i < 8; i++)
#pragma unroll
      for (int r = 0; r < 4; r++) sa[i][r] = 0.f;
#pragma unroll
    for (int c8 = 0; c8 < HC; c8++) {
      int ko = c8 * 8 + 2 * t;
      float2 q0 = *reinterpret_cast<const float2*>(&Qs[r1 * SK + ko]);
      float2 q1 = *reinterpret_cast<const float2*>(&Qs[(r1 + 8) * SK + ko]);
#pragma unroll
      for (int nc = 0; nc < 8; nc++) {
        float2 kb =
            *reinterpret_cast<const float2*>(&Ksb[(nc * 8 + g) * SK + ko]);
        mma8(sa[nc], q0.x, q1.x, q0.y, q1.y, kb.x, kb.y);
      }
    }
    // scale
#pragma unroll
    for (int nc = 0; nc < 8; nc++)
#pragma unroll
      for (int r = 0; r < 4; r++) sa[nc][r] *= p.scale;

    // online softmax per row half (h=0: row g; h=1: row g+8)
#pragma unroll
    for (int h = 0; h < 2; h++) {
      float mt = -1e30f;
#pragma unroll
      for (int nc = 0; nc < 8; nc++)
#pragma unroll
        for (int q = 0; q < 2; q++) {
          int key = kt * KT + nc * 8 + 2 * t + q;
          if (key < nloc) mt = fmaxf(mt, sa[nc][2 * h + q]);
        }
      mt = fmaxf(mt, __shfl_xor_sync(0xffffffffu, mt, 1));
      mt = fmaxf(mt, __shfl_xor_sync(0xffffffffu, mt, 2));
      float mn = fmaxf(m_run[h], mt);
      float ratio = __expf(m_run[h] - mn);
      float st = 0.f;
#pragma unroll
      for (int nc = 0; nc < 8; nc++)
#pragma unroll
        for (int q = 0; q < 2; q++) {
          int rr = 2 * h + q;
          int key = kt * KT + nc * 8 + 2 * t + q;
          float e = 0.f;
          if (key < nloc) {
            e = __expf(sa[nc][rr] - mn);
            st += e;
          }
          sa[nc][rr] = to_tf32(e);
        }
      st += __shfl_xor_sync(0xffffffffu, st, 1);
      st += __shfl_xor_sync(0xffffffffu, st, 2);
      s_run[h] = s_run[h] * ratio + st;
      m_run[h] = mn;
#pragma unroll
      for (int nc = 0; nc < 7; nc++)
#pragma unroll
        for (int q = 0; q < 2; q++) o[nc][2 * h + q] *= ratio;
    }

    // O += P @ V  (P fragment feeds mma A directly via k-slot remap)
#pragma unroll
    for (int ck = 0; ck < 8; ck++) {
      int ko = ck * 8 + 2 * t;
      float a0 = sa[ck][0], a1 = sa[ck][2], a2 = sa[ck][1], a3 = sa[ck][3];
#pragma unroll
      for (int nc = 0; nc < 7; nc++) {
        float bx = Vsb[ko * SK + nc * 8 + g];
        float by2 = Vsb[(ko + 1) * SK + nc * 8 + g];
        mma8(o[nc], a0, a1, a2, a3, bx, by2);
      }
    }
    __syncthreads();
    if (kt + 2 < T) issueKV(kt + 2, kt & 1);
    cp_commit();
  }

  const float inv0 = 1.f / s_run[0];
  const float inv1 = 1.f / s_run[1];
  float* Cb =
      p.y + (long long)(z / p.cDiv) * p.cs1 + (long long)(z % p.cDiv) * p.cs2;
#pragma unroll
  for (int nc = 0; nc < 7; nc++)
#pragma unroll
    for (int r = 0; r < 4; r++) {
      int row = m0 + warp * 16 + g + ((r >> 1) ? 8 : 0);
      int col = nc * 8 + 2 * t + (r & 1);
      if (row < nloc && col < HD) {
        float v = o[nc][r] * ((r >> 1) ? inv1 : inv0);
        v *= p.rout[((long long)(z / p.cDiv) * p.routN + row) * E +
                    (z % p.cDiv)];
        Cb[(long long)row * p.ldc + col] = to_tf32(v);
      }
    }
}

// ---------------------------------------------------------------------------
// TF32 tensor-core GEMM; cp.async 4-stage ring; k-slot remap fragments.
// EPI: 0 +bias; 1 +bias,GELU(round); 6 +bias, wide-N qkv scatter (round).
// ---------------------------------------------------------------------------
template <int BM, int BN, int WM, int WN, int BTRANS, int EPI>
__global__ __launch_bounds__(256) void tmma_k(GemmP p) {
  constexpr int BK = 16, ST = 4;
  constexpr int SKA = BK + 4;
  constexpr int LDB0 = BN + 4;
  constexpr int ASZ = BM * SKA;
  constexpr int BSZ = BTRANS ? BN * SKA : BK * LDB0;
  constexpr int NWN = BN / WN;
  constexpr int MT = WM / 16, NT = WN / 8;
  constexpr int ACH = BM * 4;
  constexpr int AV_ = (ACH + 255) / 256;
  constexpr int BV_ = BN / 64;
  static_assert((BM / WM) * (BN / WN) == 8, "need 8 warps");

  extern __shared__ float sm[];
  float* As = sm;
  float* Bs = sm + ST * ASZ;
  const uint32_t a_u32 = (uint32_t)__cvta_generic_to_shared(As);
  const uint32_t b_u32 = (uint32_t)__cvta_generic_to_shared(Bs);

  const int z = blockIdx.z;
  int seg = 0;
  if (p.zSeg) seg = z / p.zSeg;
  const int Mloc = (p.segFlags & 1) ? c_segN[seg] : p.M;
  const int Nloc = (p.segFlags & 2) ? c_segN[seg] : p.N;
  const int Kloc = (p.segFlags & 4) ? c_segN[seg] : p.K;

  const float* Ab =
      p.A + (long long)(z / p.aDiv) * p.as1 + (long long)(z % p.aDiv) * p.as2;
  const float* Bb =
      p.Bm + (long long)(z / p.bDiv) * p.bs1 + (long long)(z % p.bDiv) * p.bs2 +
      (long long)seg * p.bSeg;
  float* Cb =
      p.C + (long long)(z / p.cDiv) * p.cs1 + (long long)(z % p.cDiv) * p.cs2;

  const int m0 = blockIdx.y * BM, n0 = blockIdx.x * BN;
  const int tid = threadIdx.x;
  const int warp = tid >> 5, lane = tid & 31;
  const int g = lane >> 2, t = lane & 3;
  const int wm = (warp / NWN) * WM, wn = (warp % NWN) * WN;

  auto issue = [&](int it) {
    const int s = it % ST;
    const int kb = it * BK;
#pragma unroll
    for (int v = 0; v < AV_; v++) {
      int idx = tid + v * 256;
      if ((ACH % 256) != 0 && idx >= ACH) break;
      int m = idx >> 2, c4 = (idx & 3) * 4;
      int gm = m0 + m, gk = kb + c4;
      int by = 0;
      if (gm < Mloc) {
        int rem = (Kloc - gk) * 4;
        by = rem > 16 ? 16 : (rem > 0 ? rem : 0);
      }
      const float* src = Ab + (long long)(by ? gm : 0) * p.lda + (by ? gk : 0);
      cp16(a_u32 + (uint32_t)(s * ASZ + m * SKA + c4) * 4u, src, by);
    }
    if (BTRANS == 0) {
#pragma unroll
      for (int v = 0; v < BV_; v++) {
        int idx = tid + v * 256;
        int kk = idx / (BN / 4), n4 = (idx % (BN / 4)) * 4;
        int gk = kb + kk, gn = n0 + n4;
        int by = 0;
        if (gk < Kloc) {
          int rem = (Nloc - gn) * 4;
          by = rem > 16 ? 16 : (rem > 0 ? rem : 0);
        }
        const float* src = Bb + (long long)(by ? gk : 0) * p.ldb + (by ? gn : 0);
        cp16(b_u32 + (uint32_t)(s * BSZ + kk * LDB0 + n4) * 4u, src, by);
      }
    } else {
#pragma unroll
      for (int v = 0; v < BV_; v++) {
        int idx = tid + v * 256;
        int n = idx >> 2, c4 = (idx & 3) * 4;
        int gn = n0 + n, gk = kb + c4;
        int by = 0;
        if (gn < Nloc) {
          int rem = (Kloc - gk) * 4;
          by = rem > 16 ? 16 : (rem > 0 ? rem : 0);
        }
        const float* src = Bb + (long long)(by ? gn : 0) * p.ldb + (by ? gk : 0);
        cp16(b_u32 + (uint32_t)(s * BSZ + n * SKA + c4) * 4u, src, by);
      }
    }
  };

  float c[MT][NT][4];
#pragma unroll
  for (int i = 0; i < MT; i++)
#pragma unroll
    for (int j = 0; j < NT; j++)
#pragma unroll
      for (int r = 0; r < 4; r++) c[i][j][r] = 0.f;

  auto comp = [&](int s) {
    const float* Asb = As + s * ASZ;
    const float* Bsb = Bs + s * BSZ;
#pragma unroll
    for (int kq = 0; kq < 2; kq++) {
      const int ko = kq * 8 + 2 * t;
      float2 af[MT][2];
#pragma unroll
      for (int mt = 0; mt < MT; mt++) {
        int r0 = wm + mt * 16 + g;
        af[mt][0] = *reinterpret_cast<const float2*>(&Asb[r0 * SKA + ko]);
        af[mt][1] = *reinterpret_cast<const float2*>(&Asb[(r0 + 8) * SKA + ko]);
      }
      float bx[NT], by_[NT];
#pragma unroll
      for (int nt = 0; nt < NT; nt++) {
        int col = wn + nt * 8 + g;
        if (BTRANS == 1) {
          float2 bb = *reinterpret_cast<const float2*>(&Bsb[col * SKA + ko]);
          bx[nt] = bb.x;
          by_[nt] = bb.y;
        } else {
          bx[nt] = Bsb[ko * LDB0 + col];
          by_[nt] = Bsb[(ko + 1) * LDB0 + col];
        }
      }
#pragma unroll
      for (int mt = 0; mt < MT; mt++)
#pragma unroll
        for (int nt = 0; nt < NT; nt++)
          mma8(c[mt][nt], af[mt][0].x, af[mt][1].x, af[mt][0].y, af[mt][1].y,
               bx[nt], by_[nt]);
    }
  };

  const int iters = (Kloc + BK - 1) / BK;
#pragma unroll
  for (int s = 0; s < ST - 1; s++) {
    if (s < iters) issue(s);
    cp_commit();
  }
  for (int it = 0; it < iters; it++) {
    cp_wait<ST - 2>();
    __syncthreads();
    if (it + ST - 1 < iters) issue(it + ST - 1);
    cp_commit();
    comp(it % ST);
  }

  const float* biasb = nullptr;
  if ((EPI == 0 || EPI == 1 || EPI == 6) && p.bias)
    biasb = p.bias + (long long)(z % p.biasDiv) * p.biasS +
            (long long)seg * p.biasSeg;

#pragma unroll
  for (int mt = 0; mt < MT; mt++)
#pragma unroll
    for (int nt = 0; nt < NT; nt++)
#pragma unroll
      for (int r = 0; r < 4; r++) {
        int row = m0 + wm + mt * 16 + g + ((r >> 1) ? 8 : 0);
        int col = n0 + wn + nt * 8 + 2 * t + (r & 1);
        if (row >= Mloc || col >= Nloc) continue;
        float v = c[mt][nt][r];
        if (biasb) v += biasb[col];
        if (EPI == 1) {
          v = 0.5f * v * (1.f + erff(v * 0.70710678118654752f));
          v = to_tf32(v);
        }
        if (EPI == 6) {
          v = to_tf32(v);
          int e = col / TH;
          int th = col - e * TH;
          int h = th / HD;
          int s2 = th - h * HD;
          int b = row / p.routN;
          int i = row - b * p.routN;
          Cb[(long long)(b * E + e) * 3 * p.splitStride +
             (long long)h * p.splitStride + (long long)i * p.ldc + s2] = v;
        } else {
          Cb[(long long)row * p.ldc + col] = v;
        }
      }
}

// ---------------------------------------------------------------------------
// SIMT SGEMM (routing GEMM, N=20; fp32). z-batched via as1/bs1/cs1/biasS.
// ---------------------------------------------------------------------------
template <int BM, int BN, int BK, int TM, int TN>
__global__ __launch_bounds__((BM / TM) * (BN / TN)) void sgemm2_k(GemmP p) {
  constexpr int NTHR = (BM / TM) * (BN / TN);
  constexpr int TX = BN / TN;
  __shared__ float As[BK][BM + 4];
  __shared__ float Bs[BK][BN + 4];

  const int z = blockIdx.z;
  const float* Ab = p.A + (long long)z * p.as1;
  const float* Bb = p.Bm + (long long)z * p.bs1;
  float* Cb = p.C + (long long)z * p.cs1;
  const float* bias = p.bias ? p.bias + (long long)z * p.biasS : nullptr;

  const int m0 = blockIdx.y * BM, n0 = blockIdx.x * BN;
  const int tid = threadIdx.x;
  const int tx = tid % TX, ty = tid / TX;

  float acc[TM][TN];
#pragma unroll
  for (int i = 0; i < TM; i++)
#pragma unroll
    for (int j = 0; j < TN; j++) acc[i][j] = 0.f;

  for (int k0 = 0; k0 < p.K; k0 += BK) {
    for (int idx = tid; idx < BM * BK; idx += NTHR) {
      int m = idx / BK, kk = idx % BK;
      int gm = m0 + m, gk = k0 + kk;
      As[kk][m] = (gm < p.M && gk < p.K) ? Ab[(long long)gm * p.lda + gk] : 0.f;
    }
    for (int idx = tid; idx < BK * BN; idx += NTHR) {
      int kk = idx / BN, nn = idx % BN;
      int gk = k0 + kk, gn = n0 + nn;
      Bs[kk][nn] = (gk < p.K && gn < p.N) ? Bb[(long long)gk * p.ldb + gn] : 0.f;
    }
    __syncthreads();
#pragma unroll
    for (int kk = 0; kk < BK; kk++) {
      float a[TM], b[TN];
#pragma unroll
      for (int i = 0; i < TM; i++) a[i] = As[kk][ty * TM + i];
#pragma unroll
      for (int j = 0; j < TN; j++) b[j] = Bs[kk][tx * TN + j];
#pragma unroll
      for (int i = 0; i < TM; i++)
#pragma unroll
        for (int j = 0; j < TN; j++) acc[i][j] += a[i] * b[j];
    }
    __syncthreads();
  }

#pragma unroll
  for (int i = 0; i < TM; i++) {
    int row = m0 + ty * TM + i;
    if (row >= p.M) continue;
#pragma unroll
    for (int j = 0; j < TN; j++) {
      int col = n0 + tx * TN + j;
      if (col >= p.N) continue;
      float v = acc[i][j] + (bias ? bias[col] : 0.f);
      Cb[(long long)row * p.ldc + col] = v;
    }
  }
}

// ---------------------------------------------------------------------------
// One-launch weight prep
// ---------------------------------------------------------------------------
__global__ void prep_k(float* sc, const float* ew, const float* ow,
                       const float* w1, const float* w2) {
  const long long n_ewp = (long long)L * D * EN;
  const long long n_ow = (long long)L * D * D;
  const long long n_w1 = (long long)L * D * F;
  const long long n_w2 = (long long)L * F * D;
  long long i = (long long)blockIdx.x * blockDim.x + threadIdx.x;
  if (i < n_ewp) {
    int col = (int)(i % EN);
    long long r = i / EN;
    int d = (int)(r % D);
    int l = (int)(r / D);
    int e = col / TH, th = col - e * TH;
    sc[OFF_EWP + i] = to_tf32(ew[(((long long)l * E + e) * D + d) * TH + th]);
    return;
  }
  i -= n_ewp;
  if (i < n_ow) { sc[OFF_OWR + i] = to_tf32(ow[i]); return; }
  i -= n_ow;
  if (i < n_w1) { sc[OFF_W1R + i] = to_tf32(w1[i]); return; }
  i -= n_w1;
  if (i < n_w2) { sc[OFF_W2R + i] = to_tf32(w2[i]); }
}

// ---------------------------------------------------------------------------
// Small kernels
// ---------------------------------------------------------------------------
__global__ void copy_round_k(float* dst, const float* src, long long n) {
  long long i = (long long)blockIdx.x * blockDim.x + threadIdx.x;
  if (i < n) dst[i] = to_tf32(src[i]);
}

__global__ void gather4_k(float* t4, const float* x) {
  long long idx = (long long)blockIdx.x * blockDim.x + threadIdx.x;
  long long tot = N_ROWS4 * D;
  if (idx >= tot) return;
  int d = (int)(idx % D);
  long long r = idx / D;
  int i = (int)(r % NP);
  int b = (int)((r / NP) % B);
  int j = (int)(r / ((long long)NP * B));
  if (i >= c_segN[j]) return;
  int si = (i < c_segP1[j]) ? c_segST[j] + i : i - c_segP1[j];
  t4[idx] = x[((long long)b * S + si) * D + d];
}

__device__ __forceinline__ float seg_cnt(int i) {
  float c = 0.f;
  c += (i < 460);
  c += (i >= 256 && i < 665);
  c += (i >= 460 && i < 870);
  c += (i >= 665);
  c += (i < 51);
  return c;
}

__global__ void combine_k(float* x, const float* o4) {
  long long idx = (long long)blockIdx.x * blockDim.x + threadIdx.x;
  if (idx >= NX) return;
  int d = (int)(idx % D);
  long long r = idx / D;
  int i = (int)(r % S);
  int b = (int)(r / S);
  float s = 0.f;
  if (i < 460) s += o4[(((0 * B + b) * (long long)NP + i) * D) + d];
  if (i >= 256 && i < 665)
    s += o4[(((1 * B + b) * (long long)NP + (i - 256)) * D) + d];
  if (i >= 460 && i < 870)
    s += o4[(((2 * B + b) * (long long)NP + (i - 460)) * D) + d];
  if (i >= 665) s += o4[(((3 * B + b) * (long long)NP + (i - 665)) * D) + d];
  if (i < 51) s += o4[(((3 * B + b) * (long long)NP + (359 + i)) * D) + d];
  x[idx] = to_tf32(s / seg_cnt(i));
}

__global__ void softmaxE_k(float* r, int rows) {
  int i = blockIdx.x * blockDim.x + threadIdx.x;
  if (i >= rows) return;
  float* p = r + (long long)i * E;
  float m = -1e30f;
  for (int e = 0; e < E; e++) m = fmaxf(m, p[e]);
  float s = 0.f;
  for (int e = 0; e < E; e++) {
    float v = __expf(p[e] - m);
    p[e] = v;
    s += v;
  }
  float inv = 1.f / s;
  for (int e = 0; e < E; e++) p[e] *= inv;
}

template <bool CVT, int SEGROWS>
__global__ void add_ln_k(const float* x, const float* r, const float* g,
                         const float* b, float* out) {
  long long base = (long long)blockIdx.x * D;
  if (SEGROWS > 0) {
    int seg = blockIdx.x / SEGROWS;
    g += (long long)seg * D;
    b += (long long)seg * D;
  }
  __shared__ float buf[D];
  __shared__ float redA[32], redB[32];
  __shared__ float sh_m, sh_inv;
  int tid = threadIdx.x;
  int nw = blockDim.x >> 5;

  float s = 0.f, s2 = 0.f;
  for (int d = tid; d < D; d += blockDim.x) {
    float v = x[base + d] + r[base + d];
    buf[d] = v;
    s += v;
    s2 += v * v;
  }
  for (int o = 16; o; o >>= 1) {
    s += __shfl_xor_sync(0xffffffffu, s, o);
    s2 += __shfl_xor_sync(0xffffffffu, s2, o);
  }
  if ((tid & 31) == 0) { redA[tid >> 5] = s; redB[tid >> 5] = s2; }
  __syncthreads();
  if (tid < 32) {
    float a2 = (tid < nw) ? redA[tid] : 0.f;
    float b2 = (tid < nw) ? redB[tid] : 0.f;
    for (int o = 16; o; o >>= 1) {
      a2 += __shfl_xor_sync(0xffffffffu, a2, o);
      b2 += __shfl_xor_sync(0xffffffffu, b2, o);
    }
    if (tid == 0) {
      float mean = a2 / D;
      float var = b2 / D - mean * mean;
      sh_m = mean;
      sh_inv = rsqrtf(var + 1e-5f);
    }
  }
  __syncthreads();
  float mean = sh_m, inv = sh_inv;
  for (int d = tid; d < D; d += blockDim.x) {
    float v = (buf[d] - mean) * inv * g[d] + b[d];
    out[base + d] = CVT ? to_tf32(v) : v;
  }
}

// ---------------------------------------------------------------------------
// Host-side driver
// ---------------------------------------------------------------------------
static inline int cdiv(int a, int b) { return (a + b - 1) / b; }

struct Wts {
  const float *ew, *eb, *rw, *rb, *ow, *ob, *l1g, *l1b, *w1, *b1, *w2, *b2,
      *l2g, *l2b;
};

constexpr int SMEM_128x128_T0 = 4 * (128 * 20 + 16 * 132) * 4;  // 74752
constexpr int SMEM_FATTN = (128 * 56 + 4 * 64 * 56) * 4;        // 86016

static void run_block(float* sc, const float* t, float* out, int layer, int n,
                      const Wts& w) {
  const int M = B * n;
  float* rout = sc + OFF_ROUT;
  float* qkv = sc + OFF_QKV;
  float* y = sc + OFF_Y;
  float* a = sc + OFF_A;
  float* x1 = sc + OFF_X1;
  float* h = sc + OFF_H;
  const float* ewp = sc + OFF_EWP + (long long)layer * D * EN;
  const float* owr = sc + OFF_OWR + (long long)layer * D * D;
  const float* w1r = sc + OFF_W1R + (long long)layer * D * F;
  const float* w2r = sc + OFF_W2R + (long long)layer * F * D;

  GemmP p;
  auto reset = [&]() {
    p = GemmP{};
    p.aDiv = p.bDiv = p.cDiv = p.biasDiv = 1;
    p.scale = 1.f;
  };

  reset();
  p.A = t; p.Bm = w.rw + (long long)layer * D * E;
  p.bias = w.rb + (long long)layer * E; p.C = rout;
  p.M = M; p.N = E; p.K = D; p.lda = D; p.ldb = E; p.ldc = E;
  sgemm2_k<64, 64, 16, 4, 4><<<dim3(1, cdiv(M, 64), 1), 256>>>(p);
  softmaxE_k<<<cdiv(M, 256), 256>>>(rout, M);

  // qkv wide-N
  reset();
  p.A = t; p.lda = D;
  p.Bm = ewp; p.ldb = EN;
  p.bias = w.eb + (long long)layer * E * TH;
  p.C = qkv; p.ldc = HD_P;
  p.splitStride = (long long)n * HD_P;
  p.routN = n;
  p.M = M; p.N = EN; p.K = D;
  tmma_k<128, 128, 64, 32, 0, 6>
      <<<dim3(cdiv(EN, 128), cdiv(M, 128), 1), 256, SMEM_128x128_T0>>>(p);

  // fused attention
  {
    FaP f{};
    f.qkv = qkv;
    f.zStride = 3LL * n * HD_P;
    f.kOff = (long long)n * HD_P;
    f.vOff = 2LL * n * HD_P;
    f.y = y; f.cDiv = E; f.cs1 = (long long)n * D; f.cs2 = HD; f.ldc = D;
    f.rout = rout; f.routN = n;
    f.n = n; f.zSeg = 0;
    f.scale = 0.14142135623730950488f;
    fattn_k<<<dim3(cdiv(n, 128), B * E), 256, SMEM_FATTN>>>(f);
  }

  reset();
  p.A = y; p.lda = D;
  p.Bm = owr; p.ldb = D;
  p.bias = w.ob + (long long)layer * D;
  p.C = a; p.ldc = D;
  p.M = M; p.N = D; p.K = D;
  tmma_k<128, 128, 64, 32, 0, 0>
      <<<dim3(cdiv(D, 128), cdiv(M, 128), 1), 256, SMEM_128x128_T0>>>(p);

  add_ln_k<true, 0><<<M, 256>>>(t, a, w.l1g + (long long)layer * D,
                                w.l1b + (long long)layer * D, x1);

  reset();
  p.A = x1; p.lda = D;
  p.Bm = w1r; p.ldb = F;
  p.bias = w.b1 + (long long)layer * F;
  p.C = h; p.ldc = F;
  p.M = M; p.N = F; p.K = D;
  tmma_k<128, 128, 64, 32, 0, 1>
      <<<dim3(cdiv(F, 128), cdiv(M, 128), 1), 256, SMEM_128x128_T0>>>(p);

  reset();
  p.A = h; p.lda = F;
  p.Bm = w2r; p.ldb = D;
  p.bias = w.b2 + (long long)layer * D;
  p.C = y; p.ldc = D;
  p.M = M; p.N = D; p.K = F;
  tmma_k<128, 128, 64, 32, 0, 0>
      <<<dim3(cdiv(D, 128), cdiv(M, 128), 1), 256, SMEM_128x128_T0>>>(p);

  if (layer == L - 1)
    add_ln_k<false, 0><<<M, 256>>>(x1, y, w.l2g + (long long)layer * D,
                                   w.l2b + (long long)layer * D, out);
  else
    add_ln_k<true, 0><<<M, 256>>>(x1, y, w.l2g + (long long)layer * D,
                                  w.l2b + (long long)layer * D, out);
}

static void run_segs(float* sc, int cyc, const Wts& w) {
  const int layerBase = 1 + 4 * cyc;
  const int MROWS = B * NP;
  const int NR4 = 4 * MROWS;
  float* t4 = sc + OFF_T4;
  float* r4 = sc + OFF_R4;
  float* qkv4 = sc + OFF_QKV4;
  float* y4 = sc + OFF_Y4;
  float* a4 = sc + OFF_A4;
  float* x14 = sc + OFF_X14;
  float* h4 = sc + OFF_H4;
  float* o4 = sc + OFF_O4;

  gather4_k<<<(int)((N_ROWS4 * D + 255) / 256), 256>>>(t4, sc + OFF_X);

  GemmP p;
  auto reset = [&]() {
    p = GemmP{};
    p.aDiv = p.bDiv = p.cDiv = p.biasDiv = 1;
    p.scale = 1.f;
  };

  reset();
  p.A = t4; p.lda = D; p.as1 = (long long)MROWS * D;
  p.Bm = w.rw + (long long)layerBase * D * E; p.ldb = E; p.bs1 = (long long)D * E;
  p.bias = w.rb + (long long)layerBase * E; p.biasS = E;
  p.C = r4; p.ldc = E; p.cs1 = (long long)MROWS * E;
  p.M = MROWS; p.N = E; p.K = D;
  sgemm2_k<64, 64, 16, 4, 4><<<dim3(1, cdiv(MROWS, 64), 4), 256>>>(p);
  softmaxE_k<<<cdiv(NR4, 256), 256>>>(r4, NR4);

  reset();
  p.A = t4; p.lda = D; p.as1 = (long long)MROWS * D;
  p.Bm = sc + OFF_EWP + (long long)layerBase * D * EN; p.ldb = EN;
  p.bias = w.eb + (long long)layerBase * E * TH;
  p.C = qkv4; p.ldc = HD_P; p.cs1 = (long long)ZS * 3 * NP * HD_P;
  p.splitStride = (long long)NP * HD_P;
  p.routN = NP;
  p.M = MROWS; p.N = EN; p.K = D;
  p.zSeg = 1; p.bSeg = (long long)D * EN; p.biasSeg = (long long)E * TH;
  tmma_k<128, 128, 64, 32, 0, 6>
      <<<dim3(cdiv(EN, 128), cdiv(MROWS, 128), 4), 256, SMEM_128x128_T0>>>(p);

  // fused attention over all 160 z
  {
    FaP f{};
    f.qkv = qkv4;
    f.zStride = 3LL * NP * HD_P;
    f.kOff = (long long)NP * HD_P;
    f.vOff = 2LL * NP * HD_P;
    f.y = y4; f.cDiv = E; f.cs1 = (long long)NP * D; f.cs2 = HD; f.ldc = D;
    f.rout = r4; f.routN = NP;
    f.n = NP; f.zSeg = ZS;
    f.scale = 0.14142135623730950488f;
    fattn_k<<<dim3(cdiv(NP, 128), 4 * ZS), 256, SMEM_FATTN>>>(f);
  }

  reset();
  p.A = y4; p.lda = D; p.as1 = (long long)MROWS * D;
  p.Bm = sc + OFF_OWR + (long long)layerBase * D * D; p.ldb = D;
  p.bias = w.ob + (long long)layerBase * D;
  p.C = a4; p.ldc = D; p.cs1 = (long long)MROWS * D;
  p.M = MROWS; p.N = D; p.K = D;
  p.zSeg = 1; p.bSeg = (long long)D * D; p.biasSeg = D;
  tmma_k<128, 128, 64, 32, 0, 0>
      <<<dim3(cdiv(D, 128), cdiv(MROWS, 128), 4), 256, SMEM_128x128_T0>>>(p);

  add_ln_k<true, B * NP><<<NR4, 256>>>(
      t4, a4, w.l1g + (long long)layerBase * D, w.l1b + (long long)layerBase * D,
      x14);

  reset();
  p.A = x14; p.lda = D; p.as1 = (long long)MROWS * D;
  p.Bm = sc + OFF_W1R + (long long)layerBase * D * F; p.ldb = F;
  p.bias = w.b1 + (long long)layerBase * F;
  p.C = h4; p.ldc = F; p.cs1 = (long long)MROWS * F;
  p.M = MROWS; p.N = F; p.K = D;
  p.zSeg = 1; p.bSeg = (long long)D * F; p.biasSeg = F;
  tmma_k<128, 128, 64, 32, 0, 1>
      <<<dim3(cdiv(F, 128), cdiv(MROWS, 128), 4), 256, SMEM_128x128_T0>>>(p);

  reset();
  p.A = h4; p.lda = F; p.as1 = (long long)MROWS * F;
  p.Bm = sc + OFF_W2R + (long long)layerBase * F * D; p.ldb = D;
  p.bias = w.b2 + (long long)layerBase * D;
  p.C = y4; p.ldc = D; p.cs1 = (long long)MROWS * D;
  p.M = MROWS; p.N = D; p.K = F;
  p.zSeg = 1; p.bSeg = (long long)F * D; p.biasSeg = D;
  tmma_k<128, 128, 64, 32, 0, 0>
      <<<dim3(cdiv(D, 128), cdiv(MROWS, 128), 4), 256, SMEM_128x128_T0>>>(p);

  add_ln_k<true, B * NP><<<NR4, 256>>>(
      x14, y4, w.l2g + (long long)layerBase * D,
      w.l2b + (long long)layerBase * D, o4);

  combine_k<<<cdiv((int)NX, 256), 256>>>(sc + OFF_X, o4);
}

extern "C" void kernel_launch(void* const* d_in, const int* in_sizes, int n_in,
                              void* d_out, int out_size) {
  (void)in_sizes; (void)n_in; (void)out_size;
  float* sc = nullptr;
  cudaGetSymbolAddress((void**)&sc, g_scratch);

  cudaFuncSetAttribute((const void*)fattn_k,
                       cudaFuncAttributeMaxDynamicSharedMemorySize, SMEM_FATTN);
  cudaFuncSetAttribute((const void*)tmma_k<128, 128, 64, 32, 0, 0>,
                       cudaFuncAttributeMaxDynamicSharedMemorySize,
                       SMEM_128x128_T0);
  cudaFuncSetAttribute((const void*)tmma_k<128, 128, 64, 32, 0, 1>,
                       cudaFuncAttributeMaxDynamicSharedMemorySize,
                       SMEM_128x128_T0);
  cudaFuncSetAttribute((const void*)tmma_k<128, 128, 64, 32, 0, 6>,
                       cudaFuncAttributeMaxDynamicSharedMemorySize,
                       SMEM_128x128_T0);

  const float* x_in = (const float*)d_in[0];
  Wts w;
  w.ew = (const float*)d_in[1];  w.eb = (const float*)d_in[2];
  w.rw = (const float*)d_in[3];  w.rb = (const float*)d_in[4];
  w.ow = (const float*)d_in[5];  w.ob = (const float*)d_in[6];
  w.l1g = (const float*)d_in[7]; w.l1b = (const float*)d_in[8];
  w.w1 = (const float*)d_in[9];  w.b1 = (const float*)d_in[10];
  w.w2 = (const float*)d_in[11]; w.b2 = (const float*)d_in[12];
  w.l2g = (const float*)d_in[13]; w.l2b = (const float*)d_in[14];

  {
    const long long tot = (long long)L * D * EN + (long long)L * D * D +
                          (long long)L * D * F + (long long)L * F * D;
    prep_k<<<(int)((tot + 255) / 256), 256>>>(sc, w.ew, w.ow, w.w1, w.w2);
  }

  copy_round_k<<<cdiv((int)NX, 256), 256>>>(sc + OFF_X, x_in, NX);

  run_block(sc, sc + OFF_X, sc + OFF_X, 0, S, w);

  for (int c = 0; c < CYCLES; c++) run_segs(sc, c, w);

  run_block(sc, sc + OFF_X, (float*)d_out, 13, S, w);
}

// round 17
// speedup vs baseline: 1.2216x; 1.1252x over previous
#include <cuda_runtime.h>
#include <math.h>
#include <stdint.h>

// ---------------------------------------------------------------------------
// SLAMv2: 14-layer MoE-attention transformer, segmented schedule.
// Round 17: R16 + prefetched routing SGEMM (latency hidden, same FMA order)
// + gather4 folded into combine/LN scatter (pure copies). Numerics identical.
// ---------------------------------------------------------------------------

namespace {
constexpr int B = 2, S = 1024, D = 1000, E = 20, HD = 50, TH = 3 * HD;
constexpr int HD_P = 52;
constexpr int EN = E * TH;    // 3000 — wide qkv N
constexpr int F = 2048, CYCLES = 3, L = 14;
constexpr int NP = 460;       // padded segment length
constexpr int ZS = B * E;     // 40 z per segment

constexpr long long NX = (long long)B * S * D;
constexpr long long OFF_X    = 0;
constexpr long long OFF_XNEW = OFF_X + NX;
constexpr long long OFF_T    = OFF_XNEW + NX;
constexpr long long OFF_X1   = OFF_T + NX;
constexpr long long OFF_Y    = OFF_X1 + NX;
constexpr long long OFF_A    = OFF_Y + NX;
constexpr long long OFF_ROUT = OFF_A + NX;
constexpr long long OFF_H    = OFF_ROUT + (long long)B * S * E;
constexpr long long OFF_QKV  = OFF_H + (long long)B * S * F;
constexpr long long OFF_SC   = OFF_QKV + (long long)B * E * 3 * S * HD_P;
constexpr long long OFF_EWP  = OFF_SC + (long long)B * E * S * S;  // [L][D][EN]
constexpr long long OFF_OWR  = OFF_EWP + (long long)L * D * EN;
constexpr long long OFF_W1R  = OFF_OWR + (long long)L * D * D;
constexpr long long OFF_W2R  = OFF_W1R + (long long)L * D * F;
constexpr long long N_ROWS4  = 4LL * B * NP;            // 3680 rows
constexpr long long OFF_T4   = OFF_W2R + (long long)L * F * D;
constexpr long long OFF_R4   = OFF_T4 + N_ROWS4 * D;
constexpr long long OFF_QKV4 = OFF_R4 + N_ROWS4 * E;
constexpr long long OFF_Y4   = OFF_QKV4 + 160LL * 3 * NP * HD_P;
constexpr long long OFF_A4   = OFF_Y4 + N_ROWS4 * D;
constexpr long long OFF_X14  = OFF_A4 + N_ROWS4 * D;
constexpr long long OFF_H4   = OFF_X14 + N_ROWS4 * D;
constexpr long long OFF_O4   = OFF_H4 + N_ROWS4 * F;
constexpr long long TOTAL    = OFF_O4 + N_ROWS4 * D;
}  // namespace

__device__ float g_scratch[TOTAL];
__device__ const int c_segN[4]  = {460, 409, 410, 410};
__device__ const int c_segST[4] = {0, 256, 460, 665};
__device__ const int c_segP1[4] = {460, 409, 410, 359};

struct GemmP {
  const float* A; const float* Bm; const float* bias; float* C;
  int M, N, K, lda, ldb, ldc;
  int aDiv; long long as1, as2;
  int bDiv; long long bs1, bs2;
  int cDiv; long long cs1, cs2;
  int biasDiv; long long biasS;
  long long splitStride;
  float scale;
  const float* rout; int routN;
  int zSeg;
  long long bSeg;
  long long biasSeg;
  int segFlags;
};

struct FaP {
  const float* qkv;
  long long zStride, kOff, vOff;
  float* y; int cDiv; long long cs1, cs2; int ldc;
  const float* rout; int routN;
  int n;
  int zSeg;
  float scale;
};

__device__ __forceinline__ float to_tf32(float x) {
  asm("cvt.rna.tf32.f32 %0, %0;" : "+f"(x));
  return x;
}

__device__ __forceinline__ void cp16(uint32_t dst, const float* src, int bytes) {
  asm volatile("cp.async.cg.shared.global [%0], [%1], 16, %2;\n"
               :: "r"(dst), "l"(src), "r"(bytes));
}
__device__ __forceinline__ void cp_commit() {
  asm volatile("cp.async.commit_group;\n");
}
template <int N>
__device__ __forceinline__ void cp_wait() {
  asm volatile("cp.async.wait_group %0;\n" :: "n"(N));
}

__device__ __forceinline__ void mma8(float (&c)[4], float a0, float a1,
                                     float a2, float a3, float b0, float b1) {
  asm volatile(
      "mma.sync.aligned.m16n8k8.row.col.f32.tf32.tf32.f32 "
      "{%0,%1,%2,%3}, {%4,%5,%6,%7}, {%8,%9}, {%0,%1,%2,%3};"
      : "+f"(c[0]), "+f"(c[1]), "+f"(c[2]), "+f"(c[3])
      : "r"(__float_as_uint(a0)), "r"(__float_as_uint(a1)),
        "r"(__float_as_uint(a2)), "r"(__float_as_uint(a3)),
        "r"(__float_as_uint(b0)), "r"(__float_as_uint(b1)));
}

// ---------------------------------------------------------------------------
// Flash-style fused attention (unchanged from R16)
// ---------------------------------------------------------------------------
__global__ __launch_bounds__(256) void fattn_k(FaP p) {
  constexpr int QT = 128, KT = 64, SK = 56, HC = 7;
  extern __shared__ float sm[];
  float* Qs = sm;
  float* Ks = sm + QT * SK;
  float* Vs = Ks + 2 * KT * SK;
  const uint32_t q_u = (uint32_t)__cvta_generic_to_shared(Qs);
  const uint32_t k_u = (uint32_t)__cvta_generic_to_shared(Ks);
  const uint32_t v_u = (uint32_t)__cvta_generic_to_shared(Vs);

  const int z = blockIdx.y;
  const int nloc = p.zSeg ? c_segN[z / p.zSeg] : p.n;
  const float* Qb = p.qkv + (long long)z * p.zStride;
  const float* Kb = Qb + p.kOff;
  const float* Vb = Qb + p.vOff;

  const int m0 = blockIdx.x * QT;
  const int tid = threadIdx.x, warp = tid >> 5, lane = tid & 31;
  const int g = lane >> 2, t = lane & 3;
  const int r1 = warp * 16 + g;

  auto issueQ = [&]() {
#pragma unroll
    for (int v = 0; v < 7; v++) {
      int idx = tid + v * 256;
      int row = idx / 14, c = idx % 14;
      int gm = m0 + row;
      int by = 0;
      if (gm < nloc) {
        int rem = (HD - c * 4) * 4;
        by = rem > 16 ? 16 : (rem > 0 ? rem : 0);
      }
      const float* src = Qb + (by ? (long long)gm * HD_P + c * 4 : 0);
      cp16(q_u + (uint32_t)(row * SK + c * 4) * 4u, src, by);
    }
  };
  auto issueKV = [&](int kt, int s) {
#pragma unroll
    for (int v = 0; v < 7; v++) {
      int idx = tid + v * 256;
      int half = idx / 896;
      int rr = (idx % 896) / 14, c = idx % 14;
      int gk = kt * KT + rr;
      int by = 0;
      if (gk < nloc) {
        int rem = (HD - c * 4) * 4;
        by = rem > 16 ? 16 : (rem > 0 ? rem : 0);
      }
      const float* base = half ? Vb : Kb;
      const float* src = base + (by ? (long long)gk * HD_P + c * 4 : 0);
      uint32_t dst = (half ? v_u : k_u) +
                     (uint32_t)(s * KT * SK + rr * SK + c * 4) * 4u;
      cp16(dst, src, by);
    }
  };

  const int T = (nloc + KT - 1) / KT;
  issueQ();
  issueKV(0, 0);
  cp_commit();
  if (T > 1) issueKV(1, 1);
  cp_commit();

  float o[7][4];
#pragma unroll
  for (int i = 0; i < 7; i++)
#pragma unroll
    for (int r = 0; r < 4; r++) o[i][r] = 0.f;
  float m_run[2] = {-1e30f, -1e30f};
  float s_run[2] = {0.f, 0.f};

  for (int kt = 0; kt < T; kt++) {
    cp_wait<1>();
    __syncthreads();
    const float* Ksb = Ks + (kt & 1) * KT * SK;
    const float* Vsb = Vs + (kt & 1) * KT * SK;

    float sa[8][4];
#pragma unroll
    for (int i = 0; i < 8; i++)
#pragma unroll
      for (int r = 0; r < 4; r++) sa[i][r] = 0.f;
#pragma unroll
    for (int c8 = 0; c8 < HC; c8++) {
      int ko = c8 * 8 + 2 * t;
      float2 q0 = *reinterpret_cast<const float2*>(&Qs[r1 * SK + ko]);
      float2 q1 = *reinterpret_cast<const float2*>(&Qs[(r1 + 8) * SK + ko]);
#pragma unroll
      for (int nc = 0; nc < 8; nc++) {
        float2 kb =
            *reinterpret_cast<const float2*>(&Ksb[(nc * 8 + g) * SK + ko]);
        mma8(sa[nc], q0.x, q1.x, q0.y, q1.y, kb.x, kb.y);
      }
    }
#pragma unroll
    for (int nc = 0; nc < 8; nc++)
#pragma unroll
      for (int r = 0; r < 4; r++) sa[nc][r] *= p.scale;

#pragma unroll
    for (int h = 0; h < 2; h++) {
      float mt = -1e30f;
#pragma unroll
      for (int nc = 0; nc < 8; nc++)
#pragma unroll
        for (int q = 0; q < 2; q++) {
          int key = kt * KT + nc * 8 + 2 * t + q;
          if (key < nloc) mt = fmaxf(mt, sa[nc][2 * h + q]);
        }
      mt = fmaxf(mt, __shfl_xor_sync(0xffffffffu, mt, 1));
      mt = fmaxf(mt, __shfl_xor_sync(0xffffffffu, mt, 2));
      float mn = fmaxf(m_run[h], mt);
      float ratio = __expf(m_run[h] - mn);
      float st = 0.f;
#pragma unroll
      for (int nc = 0; nc < 8; nc++)
#pragma unroll
        for (int q = 0; q < 2; q++) {
          int rr = 2 * h + q;
          int key = kt * KT + nc * 8 + 2 * t + q;
          float e = 0.f;
          if (key < nloc) {
            e = __expf(sa[nc][rr] - mn);
            st += e;
          }
          sa[nc][rr] = to_tf32(e);
        }
      st += __shfl_xor_sync(0xffffffffu, st, 1);
      st += __shfl_xor_sync(0xffffffffu, st, 2);
      s_run[h] = s_run[h] * ratio + st;
      m_run[h] = mn;
#pragma unroll
      for (int nc = 0; nc < 7; nc++)
#pragma unroll
        for (int q = 0; q < 2; q++) o[nc][2 * h + q] *= ratio;
    }

#pragma unroll
    for (int ck = 0; ck < 8; ck++) {
      int ko = ck * 8 + 2 * t;
      float a0 = sa[ck][0], a1 = sa[ck][2], a2 = sa[ck][1], a3 = sa[ck][3];
#pragma unroll
      for (int nc = 0; nc < 7; nc++) {
        float bx = Vsb[ko * SK + nc * 8 + g];
        float by2 = Vsb[(ko + 1) * SK + nc * 8 + g];
        mma8(o[nc], a0, a1, a2, a3, bx, by2);
      }
    }
    __syncthreads();
    if (kt + 2 < T) issueKV(kt + 2, kt & 1);
    cp_commit();
  }

  const float inv0 = 1.f / s_run[0];
  const float inv1 = 1.f / s_run[1];
  float* Cb =
      p.y + (long long)(z / p.cDiv) * p.cs1 + (long long)(z % p.cDiv) * p.cs2;
#pragma unroll
  for (int nc = 0; nc < 7; nc++)
#pragma unroll
    for (int r = 0; r < 4; r++) {
      int row = m0 + warp * 16 + g + ((r >> 1) ? 8 : 0);
      int col = nc * 8 + 2 * t + (r & 1);
      if (row < nloc && col < HD) {
        float v = o[nc][r] * ((r >> 1) ? inv1 : inv0);
        v *= p.rout[((long long)(z / p.cDiv) * p.routN + row) * E +
                    (z % p.cDiv)];
        Cb[(long long)row * p.ldc + col] = to_tf32(v);
      }
    }
}

// ---------------------------------------------------------------------------
// TF32 tensor-core GEMM (unchanged from R16)
// ---------------------------------------------------------------------------
template <int BM, int BN, int WM, int WN, int BTRANS, int EPI>
__global__ __launch_bounds__(256) void tmma_k(GemmP p) {
  constexpr int BK = 16, ST = 4;
  constexpr int SKA = BK + 4;
  constexpr int LDB0 = BN + 4;
  constexpr int ASZ = BM * SKA;
  constexpr int BSZ = BTRANS ? BN * SKA : BK * LDB0;
  constexpr int NWN = BN / WN;
  constexpr int MT = WM / 16, NT = WN / 8;
  constexpr int ACH = BM * 4;
  constexpr int AV_ = (ACH + 255) / 256;
  constexpr int BV_ = BN / 64;
  static_assert((BM / WM) * (BN / WN) == 8, "need 8 warps");

  extern __shared__ float sm[];
  float* As = sm;
  float* Bs = sm + ST * ASZ;
  const uint32_t a_u32 = (uint32_t)__cvta_generic_to_shared(As);
  const uint32_t b_u32 = (uint32_t)__cvta_generic_to_shared(Bs);

  const int z = blockIdx.z;
  int seg = 0;
  if (p.zSeg) seg = z / p.zSeg;
  const int Mloc = (p.segFlags & 1) ? c_segN[seg] : p.M;
  const int Nloc = (p.segFlags & 2) ? c_segN[seg] : p.N;
  const int Kloc = (p.segFlags & 4) ? c_segN[seg] : p.K;

  const float* Ab =
      p.A + (long long)(z / p.aDiv) * p.as1 + (long long)(z % p.aDiv) * p.as2;
  const float* Bb =
      p.Bm + (long long)(z / p.bDiv) * p.bs1 + (long long)(z % p.bDiv) * p.bs2 +
      (long long)seg * p.bSeg;
  float* Cb =
      p.C + (long long)(z / p.cDiv) * p.cs1 + (long long)(z % p.cDiv) * p.cs2;

  const int m0 = blockIdx.y * BM, n0 = blockIdx.x * BN;
  const int tid = threadIdx.x;
  const int warp = tid >> 5, lane = tid & 31;
  const int g = lane >> 2, t = lane & 3;
  const int wm = (warp / NWN) * WM, wn = (warp % NWN) * WN;

  auto issue = [&](int it) {
    const int s = it % ST;
    const int kb = it * BK;
#pragma unroll
    for (int v = 0; v < AV_; v++) {
      int idx = tid + v * 256;
      if ((ACH % 256) != 0 && idx >= ACH) break;
      int m = idx >> 2, c4 = (idx & 3) * 4;
      int gm = m0 + m, gk = kb + c4;
      int by = 0;
      if (gm < Mloc) {
        int rem = (Kloc - gk) * 4;
        by = rem > 16 ? 16 : (rem > 0 ? rem : 0);
      }
      const float* src = Ab + (long long)(by ? gm : 0) * p.lda + (by ? gk : 0);
      cp16(a_u32 + (uint32_t)(s * ASZ + m * SKA + c4) * 4u, src, by);
    }
    if (BTRANS == 0) {
#pragma unroll
      for (int v = 0; v < BV_; v++) {
        int idx = tid + v * 256;
        int kk = idx / (BN / 4), n4 = (idx % (BN / 4)) * 4;
        int gk = kb + kk, gn = n0 + n4;
        int by = 0;
        if (gk < Kloc) {
          int rem = (Nloc - gn) * 4;
          by = rem > 16 ? 16 : (rem > 0 ? rem : 0);
        }
        const float* src = Bb + (long long)(by ? gk : 0) * p.ldb + (by ? gn : 0);
        cp16(b_u32 + (uint32_t)(s * BSZ + kk * LDB0 + n4) * 4u, src, by);
      }
    } else {
#pragma unroll
      for (int v = 0; v < BV_; v++) {
        int idx = tid + v * 256;
        int n = idx >> 2, c4 = (idx & 3) * 4;
        int gn = n0 + n, gk = kb + c4;
        int by = 0;
        if (gn < Nloc) {
          int rem = (Kloc - gk) * 4;
          by = rem > 16 ? 16 : (rem > 0 ? rem : 0);
        }
        const float* src = Bb + (long long)(by ? gn : 0) * p.ldb + (by ? gk : 0);
        cp16(b_u32 + (uint32_t)(s * BSZ + n * SKA + c4) * 4u, src, by);
      }
    }
  };

  float c[MT][NT][4];
#pragma unroll
  for (int i = 0; i < MT; i++)
#pragma unroll
    for (int j = 0; j < NT; j++)
#pragma unroll
      for (int r = 0; r < 4; r++) c[i][j][r] = 0.f;

  auto comp = [&](int s) {
    const float* Asb = As + s * ASZ;
    const float* Bsb = Bs + s * BSZ;
#pragma unroll
    for (int kq = 0; kq < 2; kq++) {
      const int ko = kq * 8 + 2 * t;
      float2 af[MT][2];
#pragma unroll
      for (int mt = 0; mt < MT; mt++) {
        int r0 = wm + mt * 16 + g;
        af[mt][0] = *reinterpret_cast<const float2*>(&Asb[r0 * SKA + ko]);
        af[mt][1] = *reinterpret_cast<const float2*>(&Asb[(r0 + 8) * SKA + ko]);
      }
      float bx[NT], by_[NT];
#pragma unroll
      for (int nt = 0; nt < NT; nt++) {
        int col = wn + nt * 8 + g;
        if (BTRANS == 1) {
          float2 bb = *reinterpret_cast<const float2*>(&Bsb[col * SKA + ko]);
          bx[nt] = bb.x;
          by_[nt] = bb.y;
        } else {
          bx[nt] = Bsb[ko * LDB0 + col];
          by_[nt] = Bsb[(ko + 1) * LDB0 + col];
        }
      }
#pragma unroll
      for (int mt = 0; mt < MT; mt++)
#pragma unroll
        for (int nt = 0; nt < NT; nt++)
          mma8(c[mt][nt], af[mt][0].x, af[mt][1].x, af[mt][0].y, af[mt][1].y,
               bx[nt], by_[nt]);
    }
  };

  const int iters = (Kloc + BK - 1) / BK;
#pragma unroll
  for (int s = 0; s < ST - 1; s++) {
    if (s < iters) issue(s);
    cp_commit();
  }
  for (int it = 0; it < iters; it++) {
    cp_wait<ST - 2>();
    __syncthreads();
    if (it + ST - 1 < iters) issue(it + ST - 1);
    cp_commit();
    comp(it % ST);
  }

  const float* biasb = nullptr;
  if ((EPI == 0 || EPI == 1 || EPI == 6) && p.bias)
    biasb = p.bias + (long long)(z % p.biasDiv) * p.biasS +
            (long long)seg * p.biasSeg;

#pragma unroll
  for (int mt = 0; mt < MT; mt++)
#pragma unroll
    for (int nt = 0; nt < NT; nt++)
#pragma unroll
      for (int r = 0; r < 4; r++) {
        int row = m0 + wm + mt * 16 + g + ((r >> 1) ? 8 : 0);
        int col = n0 + wn + nt * 8 + 2 * t + (r & 1);
        if (row >= Mloc || col >= Nloc) continue;
        float v = c[mt][nt][r];
        if (biasb) v += biasb[col];
        if (EPI == 1) {
          v = 0.5f * v * (1.f + erff(v * 0.70710678118654752f));
          v = to_tf32(v);
        }
        if (EPI == 6) {
          v = to_tf32(v);
          int e = col / TH;
          int th = col - e * TH;
          int h = th / HD;
          int s2 = th - h * HD;
          int b = row / p.routN;
          int i = row - b * p.routN;
          Cb[(long long)(b * E + e) * 3 * p.splitStride +
             (long long)h * p.splitStride + (long long)i * p.ldc + s2] = v;
        } else {
          Cb[(long long)row * p.ldc + col] = v;
        }
      }
}

// ---------------------------------------------------------------------------
// Routing SGEMM (fp32, N=20) with distance-1 register prefetch + double
// buffer. Compute loop / FMA order identical to the previous version ->
// bit-identical routing weights; only load scheduling changed.
// ---------------------------------------------------------------------------
template <int BM, int BN, int BK, int TM, int TN>
__global__ __launch_bounds__((BM / TM) * (BN / TN)) void sgemm3_k(GemmP p) {
  constexpr int NTHR = (BM / TM) * (BN / TN);
  constexpr int TX = BN / TN;
  constexpr int AV = (BM * BK) / NTHR;
  constexpr int BV = (BK * BN) / NTHR;
  __shared__ float As[2][BK][BM + 4];
  __shared__ float Bs[2][BK][BN + 4];

  const int z = blockIdx.z;
  const float* Ab = p.A + (long long)z * p.as1;
  const float* Bb = p.Bm + (long long)z * p.bs1;
  float* Cb = p.C + (long long)z * p.cs1;
  const float* bias = p.bias ? p.bias + (long long)z * p.biasS : nullptr;

  const int m0 = blockIdx.y * BM, n0 = blockIdx.x * BN;
  const int tid = threadIdx.x;
  const int tx = tid % TX, ty = tid / TX;

  float ar[AV], br[BV];
  auto ldA = [&](int k0) {
#pragma unroll
    for (int v = 0; v < AV; v++) {
      int idx = tid + v * NTHR;
      int m = idx / BK, kk = idx % BK;
      int gm = m0 + m, gk = k0 + kk;
      ar[v] = (gm < p.M && gk < p.K) ? Ab[(long long)gm * p.lda + gk] : 0.f;
    }
  };
  auto stA = [&](int buf) {
#pragma unroll
    for (int v = 0; v < AV; v++) {
      int idx = tid + v * NTHR;
      int m = idx / BK, kk = idx % BK;
      As[buf][kk][m] = ar[v];
    }
  };
  auto ldB = [&](int k0) {
#pragma unroll
    for (int v = 0; v < BV; v++) {
      int idx = tid + v * NTHR;
      int kk = idx / BN, nn = idx % BN;
      int gk = k0 + kk, gn = n0 + nn;
      br[v] = (gk < p.K && gn < p.N) ? Bb[(long long)gk * p.ldb + gn] : 0.f;
    }
  };
  auto stB = [&](int buf) {
#pragma unroll
    for (int v = 0; v < BV; v++) {
      int idx = tid + v * NTHR;
      int kk = idx / BN, nn = idx % BN;
      Bs[buf][kk][nn] = br[v];
    }
  };

  float acc[TM][TN];
#pragma unroll
  for (int i = 0; i < TM; i++)
#pragma unroll
    for (int j = 0; j < TN; j++) acc[i][j] = 0.f;

  const int iters = (p.K + BK - 1) / BK;
  ldA(0);
  ldB(0);
  stA(0);
  stB(0);
  __syncthreads();
  int buf = 0;
  for (int it = 0; it < iters; it++) {
    if (it + 1 < iters) {
      ldA((it + 1) * BK);
      ldB((it + 1) * BK);
    }
#pragma unroll
    for (int kk = 0; kk < BK; kk++) {
      float a[TM], b[TN];
#pragma unroll
      for (int i = 0; i < TM; i++) a[i] = As[buf][kk][ty * TM + i];
#pragma unroll
      for (int j = 0; j < TN; j++) b[j] = Bs[buf][kk][tx * TN + j];
#pragma unroll
      for (int i = 0; i < TM; i++)
#pragma unroll
        for (int j = 0; j < TN; j++) acc[i][j] += a[i] * b[j];
    }
    if (it + 1 < iters) {
      stA(buf ^ 1);
      stB(buf ^ 1);
    }
    __syncthreads();
    buf ^= 1;
  }

#pragma unroll
  for (int i = 0; i < TM; i++) {
    int row = m0 + ty * TM + i;
    if (row >= p.M) continue;
#pragma unroll
    for (int j = 0; j < TN; j++) {
      int col = n0 + tx * TN + j;
      if (col >= p.N) continue;
      float v = acc[i][j] + (bias ? bias[col] : 0.f);
      Cb[(long long)row * p.ldc + col] = v;
    }
  }
}

// ---------------------------------------------------------------------------
// One-launch weight prep
// ---------------------------------------------------------------------------
__global__ void prep_k(float* sc, const float* ew, const float* ow,
                       const float* w1, const float* w2) {
  const long long n_ewp = (long long)L * D * EN;
  const long long n_ow = (long long)L * D * D;
  const long long n_w1 = (long long)L * D * F;
  const long long n_w2 = (long long)L * F * D;
  long long i = (long long)blockIdx.x * blockDim.x + threadIdx.x;
  if (i < n_ewp) {
    int col = (int)(i % EN);
    long long r = i / EN;
    int d = (int)(r % D);
    int l = (int)(r / D);
    int e = col / TH, th = col - e * TH;
    sc[OFF_EWP + i] = to_tf32(ew[(((long long)l * E + e) * D + d) * TH + th]);
    return;
  }
  i -= n_ewp;
  if (i < n_ow) { sc[OFF_OWR + i] = to_tf32(ow[i]); return; }
  i -= n_ow;
  if (i < n_w1) { sc[OFF_W1R + i] = to_tf32(w1[i]); return; }
  i -= n_w1;
  if (i < n_w2) { sc[OFF_W2R + i] = to_tf32(w2[i]); }
}

// ---------------------------------------------------------------------------
// Small kernels
// ---------------------------------------------------------------------------
__global__ void copy_round_k(float* dst, const float* src, long long n) {
  long long i = (long long)blockIdx.x * blockDim.x + threadIdx.x;
  if (i < n) dst[i] = to_tf32(src[i]);
}

__device__ __forceinline__ void scat_t4(float v, int b, int si, int d) {
  float* t4 = g_scratch + OFF_T4;
  if (si < 460)
    t4[(((0 * B + b) * (long long)NP + si) * D) + d] = v;
  if (si >= 256 && si < 665)
    t4[(((1 * B + b) * (long long)NP + (si - 256)) * D) + d] = v;
  if (si >= 460 && si < 870)
    t4[(((2 * B + b) * (long long)NP + (si - 460)) * D) + d] = v;
  if (si >= 665)
    t4[(((3 * B + b) * (long long)NP + (si - 665)) * D) + d] = v;
  if (si < 51)
    t4[(((3 * B + b) * (long long)NP + (359 + si)) * D) + d] = v;
}

__device__ __forceinline__ float seg_cnt(int i) {
  float c = 0.f;
  c += (i < 460);
  c += (i >= 256 && i < 665);
  c += (i >= 460 && i < 870);
  c += (i >= 665);
  c += (i < 51);
  return c;
}

// combine: x = round(sum/cnt); also scatters the same value into t4 for the
// next cycle (pure copy -> numerics identical; last cycle's writes unused).
__global__ void combine_k(float* x, const float* o4) {
  long long idx = (long long)blockIdx.x * blockDim.x + threadIdx.x;
  if (idx >= NX) return;
  int d = (int)(idx % D);
  long long r = idx / D;
  int i = (int)(r % S);
  int b = (int)(r / S);
  float s = 0.f;
  if (i < 460) s += o4[(((0 * B + b) * (long long)NP + i) * D) + d];
  if (i >= 256 && i < 665)
    s += o4[(((1 * B + b) * (long long)NP + (i - 256)) * D) + d];
  if (i >= 460 && i < 870)
    s += o4[(((2 * B + b) * (long long)NP + (i - 460)) * D) + d];
  if (i >= 665) s += o4[(((3 * B + b) * (long long)NP + (i - 665)) * D) + d];
  if (i < 51) s += o4[(((3 * B + b) * (long long)NP + (359 + i)) * D) + d];
  float v = to_tf32(s / seg_cnt(i));
  x[idx] = v;
  scat_t4(v, b, i, d);
}

__global__ void softmaxE_k(float* r, int rows) {
  int i = blockIdx.x * blockDim.x + threadIdx.x;
  if (i >= rows) return;
  float* p = r + (long long)i * E;
  float m = -1e30f;
  for (int e = 0; e < E; e++) m = fmaxf(m, p[e]);
  float s = 0.f;
  for (int e = 0; e < E; e++) {
    float v = __expf(p[e] - m);
    p[e] = v;
    s += v;
  }
  float inv = 1.f / s;
  for (int e = 0; e < E; e++) p[e] *= inv;
}

// out = layernorm(x + r) * g + b. CVT rounds to tf32. SEGROWS selects per-seg
// g/b. SCAT=1 additionally scatters the written value into t4 (layer 0 only).
template <bool CVT, int SEGROWS, int SCAT = 0>
__global__ void add_ln_k(const float* x, const float* r, const float* g,
                         const float* b, float* out) {
  long long base = (long long)blockIdx.x * D;
  if (SEGROWS > 0) {
    int seg = blockIdx.x / SEGROWS;
    g += (long long)seg * D;
    b += (long long)seg * D;
  }
  __shared__ float buf[D];
  __shared__ float redA[32], redB[32];
  __shared__ float sh_m, sh_inv;
  int tid = threadIdx.x;
  int nw = blockDim.x >> 5;

  float s = 0.f, s2 = 0.f;
  for (int d = tid; d < D; d += blockDim.x) {
    float v = x[base + d] + r[base + d];
    buf[d] = v;
    s += v;
    s2 += v * v;
  }
  for (int o = 16; o; o >>= 1) {
    s += __shfl_xor_sync(0xffffffffu, s, o);
    s2 += __shfl_xor_sync(0xffffffffu, s2, o);
  }
  if ((tid & 31) == 0) { redA[tid >> 5] = s; redB[tid >> 5] = s2; }
  __syncthreads();
  if (tid < 32) {
    float a2 = (tid < nw) ? redA[tid] : 0.f;
    float b2 = (tid < nw) ? redB[tid] : 0.f;
    for (int o = 16; o; o >>= 1) {
      a2 += __shfl_xor_sync(0xffffffffu, a2, o);
      b2 += __shfl_xor_sync(0xffffffffu, b2, o);
    }
    if (tid == 0) {
      float mean = a2 / D;
      float var = b2 / D - mean * mean;
      sh_m = mean;
      sh_inv = rsqrtf(var + 1e-5f);
    }
  }
  __syncthreads();
  float mean = sh_m, inv = sh_inv;
  const int b_ = SCAT ? (int)(blockIdx.x / S) : 0;
  const int si = SCAT ? (int)(blockIdx.x % S) : 0;
  for (int d = tid; d < D; d += blockDim.x) {
    float v = (buf[d] - mean) * inv * g[d] + b[d];
    v = CVT ? to_tf32(v) : v;
    out[base + d] = v;
    if (SCAT) scat_t4(v, b_, si, d);
  }
}

// ---------------------------------------------------------------------------
// Host-side driver
// ---------------------------------------------------------------------------
static inline int cdiv(int a, int b) { return (a + b - 1) / b; }

struct Wts {
  const float *ew, *eb, *rw, *rb, *ow, *ob, *l1g, *l1b, *w1, *b1, *w2, *b2,
      *l2g, *l2b;
};

constexpr int SMEM_128x128_T0 = 4 * (128 * 20 + 16 * 132) * 4;  // 74752
constexpr int SMEM_FATTN = (128 * 56 + 4 * 64 * 56) * 4;        // 86016

static void run_block(float* sc, const float* t, float* out, int layer, int n,
                      const Wts& w) {
  const int M = B * n;
  float* rout = sc + OFF_ROUT;
  float* qkv = sc + OFF_QKV;
  float* y = sc + OFF_Y;
  float* a = sc + OFF_A;
  float* x1 = sc + OFF_X1;
  float* h = sc + OFF_H;
  const float* ewp = sc + OFF_EWP + (long long)layer * D * EN;
  const float* owr = sc + OFF_OWR + (long long)layer * D * D;
  const float* w1r = sc + OFF_W1R + (long long)layer * D * F;
  const float* w2r = sc + OFF_W2R + (long long)layer * F * D;

  GemmP p;
  auto reset = [&]() {
    p = GemmP{};
    p.aDiv = p.bDiv = p.cDiv = p.biasDiv = 1;
    p.scale = 1.f;
  };

  reset();
  p.A = t; p.Bm = w.rw + (long long)layer * D * E;
  p.bias = w.rb + (long long)layer * E; p.C = rout;
  p.M = M; p.N = E; p.K = D; p.lda = D; p.ldb = E; p.ldc = E;
  sgemm3_k<64, 64, 16, 4, 4><<<dim3(1, cdiv(M, 64), 1), 256>>>(p);
  softmaxE_k<<<cdiv(M, 256), 256>>>(rout, M);

  reset();
  p.A = t; p.lda = D;
  p.Bm = ewp; p.ldb = EN;
  p.bias = w.eb + (long long)layer * E * TH;
  p.C = qkv; p.ldc = HD_P;
  p.splitStride = (long long)n * HD_P;
  p.routN = n;
  p.M = M; p.N = EN; p.K = D;
  tmma_k<128, 128, 64, 32, 0, 6>
      <<<dim3(cdiv(EN, 128), cdiv(M, 128), 1), 256, SMEM_128x128_T0>>>(p);

  {
    FaP f{};
    f.qkv = qkv;
    f.zStride = 3LL * n * HD_P;
    f.kOff = (long long)n * HD_P;
    f.vOff = 2LL * n * HD_P;
    f.y = y; f.cDiv = E; f.cs1 = (long long)n * D; f.cs2 = HD; f.ldc = D;
    f.rout = rout; f.routN = n;
    f.n = n; f.zSeg = 0;
    f.scale = 0.14142135623730950488f;
    fattn_k<<<dim3(cdiv(n, 128), B * E), 256, SMEM_FATTN>>>(f);
  }

  reset();
  p.A = y; p.lda = D;
  p.Bm = owr; p.ldb = D;
  p.bias = w.ob + (long long)layer * D;
  p.C = a; p.ldc = D;
  p.M = M; p.N = D; p.K = D;
  tmma_k<128, 128, 64, 32, 0, 0>
      <<<dim3(cdiv(D, 128), cdiv(M, 128), 1), 256, SMEM_128x128_T0>>>(p);

  add_ln_k<true, 0><<<M, 256>>>(t, a, w.l1g + (long long)layer * D,
                                w.l1b + (long long)layer * D, x1);

  reset();
  p.A = x1; p.lda = D;
  p.Bm = w1r; p.ldb = F;
  p.bias = w.b1 + (long long)layer * F;
  p.C = h; p.ldc = F;
  p.M = M; p.N = F; p.K = D;
  tmma_k<128, 128, 64, 32, 0, 1>
      <<<dim3(cdiv(F, 128), cdiv(M, 128), 1), 256, SMEM_128x128_T0>>>(p);

  reset();
  p.A = h; p.lda = F;
  p.Bm = w2r; p.ldb = D;
  p.bias = w.b2 + (long long)layer * D;
  p.C = y; p.ldc = D;
  p.M = M; p.N = D; p.K = F;
  tmma_k<128, 128, 64, 32, 0, 0>
      <<<dim3(cdiv(D, 128), cdiv(M, 128), 1), 256, SMEM_128x128_T0>>>(p);

  if (layer == L - 1)
    add_ln_k<false, 0><<<M, 256>>>(x1, y, w.l2g + (long long)layer * D,
                                   w.l2b + (long long)layer * D, out);
  else  // layer 0: write x AND scatter into t4 for cycle 0
    add_ln_k<true, 0, 1><<<M, 256>>>(x1, y, w.l2g + (long long)layer * D,
                                     w.l2b + (long long)layer * D, out);
}

static void run_segs(float* sc, int cyc, const Wts& w) {
  const int layerBase = 1 + 4 * cyc;
  const int MROWS = B * NP;
  const int NR4 = 4 * MROWS;
  float* t4 = sc + OFF_T4;
  float* r4 = sc + OFF_R4;
  float* qkv4 = sc + OFF_QKV4;
  float* y4 = sc + OFF_Y4;
  float* a4 = sc + OFF_A4;
  float* x14 = sc + OFF_X14;
  float* h4 = sc + OFF_H4;
  float* o4 = sc + OFF_O4;

  GemmP p;
  auto reset = [&]() {
    p = GemmP{};
    p.aDiv = p.bDiv = p.cDiv = p.biasDiv = 1;
    p.scale = 1.f;
  };

  reset();
  p.A = t4; p.lda = D; p.as1 = (long long)MROWS * D;
  p.Bm = w.rw + (long long)layerBase * D * E; p.ldb = E; p.bs1 = (long long)D * E;
  p.bias = w.rb + (long long)layerBase * E; p.biasS = E;
  p.C = r4; p.ldc = E; p.cs1 = (long long)MROWS * E;
  p.M = MROWS; p.N = E; p.K = D;
  sgemm3_k<64, 64, 16, 4, 4><<<dim3(1, cdiv(MROWS, 64), 4), 256>>>(p);
  softmaxE_k<<<cdiv(NR4, 256), 256>>>(r4, NR4);

  reset();
  p.A = t4; p.lda = D; p.as1 = (long long)MROWS * D;
  p.Bm = sc + OFF_EWP + (long long)layerBase * D * EN; p.ldb = EN;
  p.bias = w.eb + (long long)layerBase * E * TH;
  p.C = qkv4; p.ldc = HD_P; p.cs1 = (long long)ZS * 3 * NP * HD_P;
  p.splitStride = (long long)NP * HD_P;
  p.routN = NP;
  p.M = MROWS; p.N = EN; p.K = D;
  p.zSeg = 1; p.bSeg = (long long)D * EN; p.biasSeg = (long long)E * TH;
  tmma_k<128, 128, 64, 32, 0, 6>
      <<<dim3(cdiv(EN, 128), cdiv(MROWS, 128), 4), 256, SMEM_128x128_T0>>>(p);

  {
    FaP f{};
    f.qkv = qkv4;
    f.zStride = 3LL * NP * HD_P;
    f.kOff = (long long)NP * HD_P;
    f.vOff = 2LL * NP * HD_P;
    f.y = y4; f.cDiv = E; f.cs1 = (long long)NP * D; f.cs2 = HD; f.ldc = D;
    f.rout = r4; f.routN = NP;
    f.n = NP; f.zSeg = ZS;
    f.scale = 0.14142135623730950488f;
    fattn_k<<<dim3(cdiv(NP, 128), 4 * ZS), 256, SMEM_FATTN>>>(f);
  }

  reset();
  p.A = y4; p.lda = D; p.as1 = (long long)MROWS * D;
  p.Bm = sc + OFF_OWR + (long long)layerBase * D * D; p.ldb = D;
  p.bias = w.ob + (long long)layerBase * D;
  p.C = a4; p.ldc = D; p.cs1 = (long long)MROWS * D;
  p.M = MROWS; p.N = D; p.K = D;
  p.zSeg = 1; p.bSeg = (long long)D * D; p.biasSeg = D;
  tmma_k<128, 128, 64, 32, 0, 0>
      <<<dim3(cdiv(D, 128), cdiv(MROWS, 128), 4), 256, SMEM_128x128_T0>>>(p);

  add_ln_k<true, B * NP><<<NR4, 256>>>(
      t4, a4, w.l1g + (long long)layerBase * D, w.l1b + (long long)layerBase * D,
      x14);

  reset();
  p.A = x14; p.lda = D; p.as1 = (long long)MROWS * D;
  p.Bm = sc + OFF_W1R + (long long)layerBase * D * F; p.ldb = F;
  p.bias = w.b1 + (long long)layerBase * F;
  p.C = h4; p.ldc = F; p.cs1 = (long long)MROWS * F;
  p.M = MROWS; p.N = F; p.K = D;
  p.zSeg = 1; p.bSeg = (long long)D * F; p.biasSeg = F;
  tmma_k<128, 128, 64, 32, 0, 1>
      <<<dim3(cdiv(F, 128), cdiv(MROWS, 128), 4), 256, SMEM_128x128_T0>>>(p);

  reset();
  p.A = h4; p.lda = F; p.as1 = (long long)MROWS * F;
  p.Bm = sc + OFF_W2R + (long long)layerBase * F * D; p.ldb = D;
  p.bias = w.b2 + (long long)layerBase * D;
  p.C = y4; p.ldc = D; p.cs1 = (long long)MROWS * D;
  p.M = MROWS; p.N = D; p.K = F;
  p.zSeg = 1; p.bSeg = (long long)F * D; p.biasSeg = D;
  tmma_k<128, 128, 64, 32, 0, 0>
      <<<dim3(cdiv(D, 128), cdiv(MROWS, 128), 4), 256, SMEM_128x128_T0>>>(p);

  add_ln_k<true, B * NP><<<NR4, 256>>>(
      x14, y4, w.l2g + (long long)layerBase * D,
      w.l2b + (long long)layerBase * D, o4);

  combine_k<<<cdiv((int)NX, 256), 256>>>(sc + OFF_X, o4);
}

extern "C" void kernel_launch(void* const* d_in, const int* in_sizes, int n_in,
                              void* d_out, int out_size) {
  (void)in_sizes; (void)n_in; (void)out_size;
  float* sc = nullptr;
  cudaGetSymbolAddress((void**)&sc, g_scratch);

  cudaFuncSetAttribute((const void*)fattn_k,
                       cudaFuncAttributeMaxDynamicSharedMemorySize, SMEM_FATTN);
  cudaFuncSetAttribute((const void*)tmma_k<128, 128, 64, 32, 0, 0>,
                       cudaFuncAttributeMaxDynamicSharedMemorySize,
                       SMEM_128x128_T0);
  cudaFuncSetAttribute((const void*)tmma_k<128, 128, 64, 32, 0, 1>,
                       cudaFuncAttributeMaxDynamicSharedMemorySize,
                       SMEM_128x128_T0);
  cudaFuncSetAttribute((const void*)tmma_k<128, 128, 64, 32, 0, 6>,
                       cudaFuncAttributeMaxDynamicSharedMemorySize,
                       SMEM_128x128_T0);

  const float* x_in = (const float*)d_in[0];
  Wts w;
  w.ew = (const float*)d_in[1];  w.eb = (const float*)d_in[2];
  w.rw = (const float*)d_in[3];  w.rb = (const float*)d_in[4];
  w.ow = (const float*)d_in[5];  w.ob = (const float*)d_in[6];
  w.l1g = (const float*)d_in[7]; w.l1b = (const float*)d_in[8];
  w.w1 = (const float*)d_in[9];  w.b1 = (const float*)d_in[10];
  w.w2 = (const float*)d_in[11]; w.b2 = (const float*)d_in[12];
  w.l2g = (const float*)d_in[13]; w.l2b = (const float*)d_in[14];

  {
    const long long tot = (long long)L * D * EN + (long long)L * D * D +
                          (long long)L * D * F + (long long)L * F * D;
    prep_k<<<(int)((tot + 255) / 256), 256>>>(sc, w.ew, w.ow, w.w1, w.w2);
  }

  copy_round_k<<<cdiv((int)NX, 256), 256>>>(sc + OFF_X, x_in, NX);

  // Block 0 writes x AND scatters into t4 (cycle 0's gather).
  run_block(sc, sc + OFF_X, sc + OFF_X, 0, S, w);

  for (int c = 0; c < CYCLES; c++) run_segs(sc, c, w);

  run_block(sc, sc + OFF_X, (float*)d_out, 13, S, w);
}